// round 7
// baseline (speedup 1.0000x reference)
#include <cuda_runtime.h>
#include <cuda_bf16.h>
#include <cstdint>

// Problem constants: B=8, H=W=64, N=4096, C=256, nh=8, nh2=4, hd=32, sr=8
#define BATCH 8
#define NTOK 4096
#define CH 256

// ---------------------------------------------------------------------------
// Scratch (device globals)
// ---------------------------------------------------------------------------
__device__ uint32_t g_xp  [(size_t)BATCH * NTOK * CH];   // x packed (hi,lo)
__device__ uint32_t g_qp  [(size_t)BATCH * NTOK * CH];   // q packed
__device__ uint32_t g_catp[(size_t)BATCH * NTOK * CH];   // cat packed
__device__ uint32_t g_x1p [BATCH * 256 * CH];
__device__ uint32_t g_x2p [BATCH * 64 * CH];
__device__ float    g_kv1 [BATCH * 256 * CH];
__device__ float    g_kv2 [BATCH * 64 * CH];
__device__ uint32_t g_k1p [BATCH * 256 * 128];
__device__ uint32_t g_k2p [BATCH * 64 * 128];
__device__ uint32_t g_v1p [BATCH * 4 * 32 * 256];        // V^T packed [b,h][e][s]
__device__ uint32_t g_v2p [BATCH * 4 * 32 * 64];
// weight splits
__device__ __nv_bfloat16 g_qwh [256 * 256], g_qwl [256 * 256];
__device__ __nv_bfloat16 g_k1wh[256 * 256], g_k1wl[256 * 256];
__device__ __nv_bfloat16 g_k2wh[256 * 256], g_k2wl[256 * 256];
__device__ __nv_bfloat16 g_pwh [256 * 256], g_pwl [256 * 256];

// ---------------------------------------------------------------------------
// helpers
// ---------------------------------------------------------------------------
__device__ __forceinline__ uint32_t pack_hilo(float v) {
    __nv_bfloat16 h = __float2bfloat16(v);
    __nv_bfloat16 l = __float2bfloat16(v - __bfloat162float(h));
    return (uint32_t)__bfloat16_as_ushort(h) |
           ((uint32_t)__bfloat16_as_ushort(l) << 16);
}

__device__ __forceinline__ void mma16816(
    float* c, const uint32_t* a, const uint32_t* b)
{
    asm volatile(
        "mma.sync.aligned.m16n8k16.row.col.f32.bf16.bf16.f32 "
        "{%0,%1,%2,%3}, {%4,%5,%6,%7}, {%8,%9}, {%0,%1,%2,%3};"
        : "+f"(c[0]), "+f"(c[1]), "+f"(c[2]), "+f"(c[3])
        : "r"(a[0]), "r"(a[1]), "r"(a[2]), "r"(a[3]), "r"(b[0]), "r"(b[1]));
}

__device__ __forceinline__ void cpa16(void* dst, const void* src) {
    uint32_t d = (uint32_t)__cvta_generic_to_shared(dst);
    asm volatile("cp.async.cg.shared.global [%0], [%1], 16;\n"
                 :: "r"(d), "l"(src));
}

// ---------------------------------------------------------------------------
// Pipelined tensor-core GEMM body (verified). K=256, N=256.
// ---------------------------------------------------------------------------
template<int MODE>
__device__ __forceinline__ void gemm_body(
    const uint32_t* __restrict__ A,
    const __nv_bfloat16* __restrict__ Wh,
    const __nv_bfloat16* __restrict__ Wl,
    const float* __restrict__ bias,
    float* __restrict__ Cf, uint32_t* __restrict__ Cp,
    int m0, char* smraw)
{
    constexpr int LDA = 40;
    constexpr int LDB = 40;
    constexpr int ASZ = 128 * LDA;
    constexpr int BSZ = 256 * LDB;

    uint32_t*      Ap = (uint32_t*)smraw;
    __nv_bfloat16* Bh = (__nv_bfloat16*)(Ap + 3 * ASZ);
    __nv_bfloat16* Bl = Bh + 3 * BSZ;

    const int tid = threadIdx.x;
    const int w = tid >> 5, lane = tid & 31;
    const int wm = w & 3, wn = w >> 2;
    const int g = lane >> 2, qk = (lane & 3) * 2;

    auto load_stage = [&](int s, int k0) {
#pragma unroll
        for (int i = 0; i < 2; i++) {
            const int c = tid + i * 512;
            const int row = c >> 3, ch = c & 7;
            cpa16(&Ap[s * ASZ + row * LDA + ch * 4],
                  &A[(size_t)(m0 + row) * 256 + k0 + ch * 4]);
        }
#pragma unroll
        for (int i = 0; i < 2; i++) {
            const int c = tid + i * 512;
            const int row = c >> 2, ch = c & 3;
            cpa16(&Bh[s * BSZ + row * LDB + ch * 8],
                  &Wh[(size_t)row * 256 + k0 + ch * 8]);
        }
#pragma unroll
        for (int i = 0; i < 2; i++) {
            const int c = tid + i * 512;
            const int row = c >> 2, ch = c & 3;
            cpa16(&Bl[s * BSZ + row * LDB + ch * 8],
                  &Wl[(size_t)row * 256 + k0 + ch * 8]);
        }
        asm volatile("cp.async.commit_group;\n" ::: "memory");
    };

    float acc[2][8][4];
#pragma unroll
    for (int mt = 0; mt < 2; mt++)
#pragma unroll
        for (int nt = 0; nt < 8; nt++)
#pragma unroll
            for (int r = 0; r < 4; r++) acc[mt][nt][r] = 0.f;

    load_stage(0, 0);
    load_stage(1, 32);

    for (int it = 0; it < 8; it++) {
        if (it < 7) asm volatile("cp.async.wait_group 1;\n" ::: "memory");
        else        asm volatile("cp.async.wait_group 0;\n" ::: "memory");
        __syncthreads();
        if (it + 2 < 8) load_stage((it + 2) % 3, (it + 2) * 32);

        const int s = it % 3;
        const uint32_t*      As  = Ap + s * ASZ;
        const __nv_bfloat16* Bhs = Bh + s * BSZ;
        const __nv_bfloat16* Bls = Bl + s * BSZ;

#pragma unroll
        for (int ks = 0; ks < 2; ks++) {
            const int kb = ks * 16;
            uint32_t ah[2][4], al[2][4];
#pragma unroll
            for (int mt = 0; mt < 2; mt++) {
                const int row = wm * 32 + mt * 16 + g;
                uint2 p0 = *(const uint2*)&As[row * LDA + kb + qk];
                uint2 p1 = *(const uint2*)&As[(row + 8) * LDA + kb + qk];
                uint2 p2 = *(const uint2*)&As[row * LDA + kb + qk + 8];
                uint2 p3 = *(const uint2*)&As[(row + 8) * LDA + kb + qk + 8];
                ah[mt][0] = __byte_perm(p0.x, p0.y, 0x5410);
                al[mt][0] = __byte_perm(p0.x, p0.y, 0x7632);
                ah[mt][1] = __byte_perm(p1.x, p1.y, 0x5410);
                al[mt][1] = __byte_perm(p1.x, p1.y, 0x7632);
                ah[mt][2] = __byte_perm(p2.x, p2.y, 0x5410);
                al[mt][2] = __byte_perm(p2.x, p2.y, 0x7632);
                ah[mt][3] = __byte_perm(p3.x, p3.y, 0x5410);
                al[mt][3] = __byte_perm(p3.x, p3.y, 0x7632);
            }
            uint32_t bf[8][2];
#pragma unroll
            for (int nt = 0; nt < 8; nt++) {
                const __nv_bfloat16* pb = &Bhs[(wn * 64 + nt * 8 + g) * LDB + kb + qk];
                bf[nt][0] = *(const uint32_t*)pb;
                bf[nt][1] = *(const uint32_t*)(pb + 8);
            }
#pragma unroll
            for (int mt = 0; mt < 2; mt++)
#pragma unroll
                for (int nt = 0; nt < 8; nt++) {
                    mma16816(acc[mt][nt], ah[mt], bf[nt]);
                    mma16816(acc[mt][nt], al[mt], bf[nt]);
                }
#pragma unroll
            for (int nt = 0; nt < 8; nt++) {
                const __nv_bfloat16* pb = &Bls[(wn * 64 + nt * 8 + g) * LDB + kb + qk];
                bf[nt][0] = *(const uint32_t*)pb;
                bf[nt][1] = *(const uint32_t*)(pb + 8);
            }
#pragma unroll
            for (int mt = 0; mt < 2; mt++)
#pragma unroll
                for (int nt = 0; nt < 8; nt++)
                    mma16816(acc[mt][nt], ah[mt], bf[nt]);
        }
        __syncthreads();
    }

#pragma unroll
    for (int mt = 0; mt < 2; mt++) {
        const int r = m0 + wm * 32 + mt * 16 + g;
#pragma unroll
        for (int nt = 0; nt < 8; nt++) {
            const int col = wn * 64 + nt * 8 + qk;
            if constexpr (MODE == 0) {
                const float b0 = bias[col], b1 = bias[col + 1];
                *(float2*)&Cf[(size_t)r * 256 + col] =
                    make_float2(acc[mt][nt][0] + b0, acc[mt][nt][1] + b1);
                *(float2*)&Cf[(size_t)(r + 8) * 256 + col] =
                    make_float2(acc[mt][nt][2] + b0, acc[mt][nt][3] + b1);
            } else if constexpr (MODE == 1) {
                *(uint2*)&Cp[(size_t)r * 256 + col] =
                    make_uint2(pack_hilo(acc[mt][nt][0]), pack_hilo(acc[mt][nt][1]));
                *(uint2*)&Cp[(size_t)(r + 8) * 256 + col] =
                    make_uint2(pack_hilo(acc[mt][nt][2]), pack_hilo(acc[mt][nt][3]));
            } else {
                *(float2*)&Cf[(size_t)r * 256 + col] =
                    make_float2(acc[mt][nt][0], acc[mt][nt][1]);
                *(float2*)&Cf[(size_t)(r + 8) * 256 + col] =
                    make_float2(acc[mt][nt][2], acc[mt][nt][3]);
                if (col < 128) {
                    *(uint2*)&Cp[(size_t)r * 128 + col] =
                        make_uint2(pack_hilo(acc[mt][nt][0]), pack_hilo(acc[mt][nt][1]));
                    *(uint2*)&Cp[(size_t)(r + 8) * 128 + col] =
                        make_uint2(pack_hilo(acc[mt][nt][2]), pack_hilo(acc[mt][nt][3]));
                }
            }
        }
    }
}

// Combined projection GEMMs: q (256 blocks) + kv1 (16) + kv2 (4).
__global__ __launch_bounds__(512) void gemm_all(
    const uint32_t* __restrict__ xp,
    const uint32_t* __restrict__ x1p, const uint32_t* __restrict__ x2p,
    const __nv_bfloat16* __restrict__ qwh, const __nv_bfloat16* __restrict__ qwl,
    const __nv_bfloat16* __restrict__ k1wh, const __nv_bfloat16* __restrict__ k1wl,
    const __nv_bfloat16* __restrict__ k2wh, const __nv_bfloat16* __restrict__ k2wl,
    uint32_t* __restrict__ qp,
    float* __restrict__ kv1, uint32_t* __restrict__ k1p,
    float* __restrict__ kv2, uint32_t* __restrict__ k2p)
{
    extern __shared__ __align__(16) char smraw[];
    if (blockIdx.x < 256)
        gemm_body<1>(xp, qwh, qwl, nullptr, nullptr, qp, blockIdx.x * 128, smraw);
    else if (blockIdx.x < 272)
        gemm_body<2>(x1p, k1wh, k1wl, nullptr, kv1, k1p, (blockIdx.x - 256) * 128, smraw);
    else
        gemm_body<2>(x2p, k2wh, k2wl, nullptr, kv2, k2p, (blockIdx.x - 272) * 128, smraw);
}

// Output projection.
__global__ __launch_bounds__(512) void gemm_proj(
    const uint32_t* __restrict__ A,
    const __nv_bfloat16* __restrict__ Wh, const __nv_bfloat16* __restrict__ Wl,
    const float* __restrict__ bias, float* __restrict__ Cf)
{
    extern __shared__ __align__(16) char smraw[];
    gemm_body<0>(A, Wh, Wl, bias, Cf, nullptr, blockIdx.x * 128, smraw);
}

// ---------------------------------------------------------------------------
// LN + exact GELU block helper (per 256-thread window group)
// ---------------------------------------------------------------------------
__device__ __forceinline__ float ln_gelu_block(
    float a, const float* __restrict__ g, const float* __restrict__ bln,
    float* red, int c)
{
    float s1 = a, s2 = a * a;
#pragma unroll
    for (int o = 16; o > 0; o >>= 1) {
        s1 += __shfl_xor_sync(0xffffffffu, s1, o);
        s2 += __shfl_xor_sync(0xffffffffu, s2, o);
    }
    if ((c & 31) == 0) { red[c >> 5] = s1; red[8 + (c >> 5)] = s2; }
    __syncthreads();
    if (c == 0) {
        float a0 = 0.f, b0 = 0.f;
#pragma unroll
        for (int i = 0; i < 8; i++) { a0 += red[i]; b0 += red[8 + i]; }
        red[0] = a0; red[8] = b0;
    }
    __syncthreads();
    const float mean = red[0] * (1.f / 256.f);
    const float var  = red[8] * (1.f / 256.f) - mean * mean;
    float y = (a - mean) * rsqrtf(var + 1e-5f) * g[c] + bln[c];
    y = 0.5f * y * (1.0f + erff(y * 0.70710678118654752f));
    __syncthreads();
    return y;
}

// ---------------------------------------------------------------------------
// dwconv_fused + x-pack + weight split:
//   blocks [0,256): two 8x8 windows each, emits x1p/x2p AND packed x (xp)
//   blocks [256,768): split 4 weight matrices into hi/lo bf16
// ---------------------------------------------------------------------------
__global__ __launch_bounds__(512) void dwconv_wsplit(
    const float* __restrict__ x, uint32_t* __restrict__ xp,
    const float* __restrict__ w1, const float* __restrict__ b1c,
    const float* __restrict__ g1, const float* __restrict__ bl1,
    const float* __restrict__ w2, const float* __restrict__ b2c,
    const float* __restrict__ g2, const float* __restrict__ bl2,
    uint32_t* __restrict__ x1p, uint32_t* __restrict__ x2p,
    const float* __restrict__ w0m, const float* __restrict__ w1m,
    const float* __restrict__ w2m, const float* __restrict__ w3m,
    __nv_bfloat16* __restrict__ h0, __nv_bfloat16* __restrict__ l0,
    __nv_bfloat16* __restrict__ h1, __nv_bfloat16* __restrict__ l1,
    __nv_bfloat16* __restrict__ h2, __nv_bfloat16* __restrict__ l2,
    __nv_bfloat16* __restrict__ h3, __nv_bfloat16* __restrict__ l3)
{
    if (blockIdx.x >= 256) {
        // weight split: 512 blocks x 512 threads, 4 matrices of 65536
        const int widx = blockIdx.x - 256;
        const int which = widx >> 7;
        const int i = (widx & 127) * 512 + threadIdx.x;
        const float* in = which == 0 ? w0m : which == 1 ? w1m : which == 2 ? w2m : w3m;
        __nv_bfloat16* oh = which == 0 ? h0 : which == 1 ? h1 : which == 2 ? h2 : h3;
        __nv_bfloat16* ol = which == 0 ? l0 : which == 1 ? l1 : which == 2 ? l2 : l3;
        const float v = in[i];
        const __nv_bfloat16 hi = __float2bfloat16(v);
        oh[i] = hi;
        ol[i] = __float2bfloat16(v - __bfloat162float(hi));
        return;
    }

    extern __shared__ float sw[];
    float* w2s = sw;                 // [64][257]
    float* w1s = sw + 64 * 257;      // [16][257]
    float* redb = sw + 80 * 257;     // [2][16]

    const int tid = threadIdx.x;
    const int c = tid & 255;
    const int win = tid >> 8;
    float* red = redb + win * 16;

    const int b = blockIdx.x >> 5;
    const int pair = blockIdx.x & 31;
    const int t2 = pair * 2 + win;
    const int oh2 = t2 >> 3, ow2 = t2 & 7;

    for (int i = tid; i < 64 * 256; i += 512)
        w2s[(i & 63) * 257 + (i >> 6)] = w2[i];
    for (int i = tid; i < 16 * 256; i += 512)
        w1s[(i & 15) * 257 + (i >> 4)] = w1[i];
    __syncthreads();

    float acc2 = b2c[c];
    float acc1[2][2];
    acc1[0][0] = acc1[0][1] = acc1[1][0] = acc1[1][1] = b1c[c];

#pragma unroll
    for (int kh = 0; kh < 8; kh++) {
#pragma unroll
        for (int kw = 0; kw < 8; kw++) {
            const int ih = oh2 * 8 + kh, iw = ow2 * 8 + kw;
            const size_t xi = ((size_t)b * NTOK + ih * 64 + iw) * CH + c;
            const float xv = x[xi];
            xp[xi] = pack_hilo(xv);              // side product: packed x
            acc2 += xv * w2s[(kh * 8 + kw) * 257 + c];
            acc1[kh >> 2][kw >> 2] += xv * w1s[((kh & 3) * 4 + (kw & 3)) * 257 + c];
        }
    }

    const float y2 = ln_gelu_block(acc2, g2, bl2, red, c);
    x2p[((size_t)b * 64 + t2) * CH + c] = pack_hilo(y2);
#pragma unroll
    for (int i = 0; i < 2; i++)
#pragma unroll
        for (int j = 0; j < 2; j++) {
            const float y1 = ln_gelu_block(acc1[i][j], g1, bl1, red, c);
            const int t1 = (oh2 * 2 + i) * 16 + (ow2 * 2 + j);
            x1p[((size_t)b * 256 + t1) * CH + c] = pack_hilo(y1);
        }
}

// ---------------------------------------------------------------------------
// Fused v local conv (+residual) -> packed V^T [b,h][e][s]; both branches.
// ---------------------------------------------------------------------------
__global__ __launch_bounds__(128) void vconv_fused(
    const float* __restrict__ kv1, const float* __restrict__ lcw1,
    const float* __restrict__ lcb1, uint32_t* __restrict__ v1p,
    const float* __restrict__ kv2, const float* __restrict__ lcw2,
    const float* __restrict__ lcb2, uint32_t* __restrict__ v2p)
{
    int token, HS;
    const float *kv, *lcw, *lcb;
    uint32_t* vtp;
    if (blockIdx.x < BATCH * 256) {
        token = blockIdx.x; HS = 16; kv = kv1; lcw = lcw1; lcb = lcb1; vtp = v1p;
    } else {
        token = blockIdx.x - BATCH * 256; HS = 8; kv = kv2; lcw = lcw2; lcb = lcb2; vtp = v2p;
    }
    const int NS = HS * HS;
    const int b  = token / NS;
    const int s  = token - b * NS;
    const int hs = s / HS, ws = s - hs * HS;
    const int c  = threadIdx.x;

    float acc = lcb[c];
#pragma unroll
    for (int kh = 0; kh < 3; kh++)
#pragma unroll
        for (int kw = 0; kw < 3; kw++) {
            const int ih = hs - 1 + kh, iw = ws - 1 + kw;
            if (ih >= 0 && ih < HS && iw >= 0 && iw < HS)
                acc += kv[((size_t)b * NS + ih * HS + iw) * 256 + 128 + c]
                     * lcw[c * 9 + kh * 3 + kw];
        }
    const float v = kv[(size_t)token * 256 + 128 + c] + acc;
    const int h = c >> 5, e = c & 31;
    vtp[(((size_t)b * 4 + h) * 32 + e) * NS + s] = pack_hilo(v);
}

// ---------------------------------------------------------------------------
// Attention via mma, 128-query tiles, 512 threads.
// ---------------------------------------------------------------------------
template<int NS>
__global__ __launch_bounds__(512) void attn_mma(
    const uint32_t* __restrict__ qp,
    const uint32_t* __restrict__ kp,
    const uint32_t* __restrict__ vtp,
    uint32_t* __restrict__ catp,
    int qoff, int ooff)
{
    constexpr int NSP = NS + 2;
    constexpr int LDQ = 34;
    constexpr int NT  = NS / 32;       // phase-1 subtiles per warp (n-tile NS/4)
    constexpr int LOG = (NS == 256) ? 8 : 6;
    const float scale = 0.17677669529663689f;

    extern __shared__ float smf[];
    uint32_t* Qs = (uint32_t*)smf;                 // [128][LDQ]
    uint32_t* Ks = Qs + 128 * LDQ;                 // [NS][LDQ]
    float*    Ss = (float*)(Ks + NS * LDQ);        // [128][NSP]
    float*    rs = Ss + 128 * NSP;                 // [128]
    uint32_t* Vs = Ks;                             // alias [32][NSP]
    uint32_t* Sp = (uint32_t*)Ss;

    const int b = blockIdx.x >> 2, h = blockIdx.x & 3;
    const int q0 = blockIdx.y * 128;
    const int tid = threadIdx.x, lane = tid & 31, w = tid >> 5;
    const int g = lane >> 2, qk = (lane & 3) * 2;

    for (int i = tid; i < 128 * 32; i += 512) {
        const int r = i >> 5, e = i & 31;
        Qs[r * LDQ + e] = qp[((size_t)(b * 4096 + q0 + r)) * 256 + qoff + h * 32 + e];
    }
    for (int i = tid; i < NS * 32; i += 512) {
        const int s = i >> 5, e = i & 31;
        Ks[s * LDQ + e] = kp[((size_t)(b * NS + s)) * 128 + h * 32 + e];
    }
    __syncthreads();

    // ---- phase 1: S = Q K^T.  16 warps: 4m (32q) x 4n (NS/4 s) ----
    {
        const int wm = w & 3, wn = w >> 2;
        float acc[2][NT][4];
#pragma unroll
        for (int mt = 0; mt < 2; mt++)
#pragma unroll
            for (int nt = 0; nt < NT; nt++)
#pragma unroll
                for (int r = 0; r < 4; r++) acc[mt][nt][r] = 0.f;

#pragma unroll
        for (int kc = 0; kc < 2; kc++) {
            const int kb = kc * 16;
            uint32_t ah[2][4], al[2][4];
#pragma unroll
            for (int mt = 0; mt < 2; mt++) {
                const int row = wm * 32 + mt * 16 + g;
                uint2 p0 = *(const uint2*)&Qs[row * LDQ + kb + qk];
                uint2 p1 = *(const uint2*)&Qs[(row + 8) * LDQ + kb + qk];
                uint2 p2 = *(const uint2*)&Qs[row * LDQ + kb + qk + 8];
                uint2 p3 = *(const uint2*)&Qs[(row + 8) * LDQ + kb + qk + 8];
                ah[mt][0] = __byte_perm(p0.x, p0.y, 0x5410);
                al[mt][0] = __byte_perm(p0.x, p0.y, 0x7632);
                ah[mt][1] = __byte_perm(p1.x, p1.y, 0x5410);
                al[mt][1] = __byte_perm(p1.x, p1.y, 0x7632);
                ah[mt][2] = __byte_perm(p2.x, p2.y, 0x5410);
                al[mt][2] = __byte_perm(p2.x, p2.y, 0x7632);
                ah[mt][3] = __byte_perm(p3.x, p3.y, 0x5410);
                al[mt][3] = __byte_perm(p3.x, p3.y, 0x7632);
            }
#pragma unroll
            for (int nt = 0; nt < NT; nt++) {
                const int srow = wn * (NS / 4) + nt * 8 + g;
                uint2 p0 = *(const uint2*)&Ks[srow * LDQ + kb + qk];
                uint2 p1 = *(const uint2*)&Ks[srow * LDQ + kb + qk + 8];
                uint32_t bh[2], bl[2];
                bh[0] = __byte_perm(p0.x, p0.y, 0x5410);
                bl[0] = __byte_perm(p0.x, p0.y, 0x7632);
                bh[1] = __byte_perm(p1.x, p1.y, 0x5410);
                bl[1] = __byte_perm(p1.x, p1.y, 0x7632);
#pragma unroll
                for (int mt = 0; mt < 2; mt++) {
                    mma16816(acc[mt][nt], ah[mt], bh);
                    mma16816(acc[mt][nt], al[mt], bh);
                    mma16816(acc[mt][nt], ah[mt], bl);
                }
            }
        }
#pragma unroll
        for (int mt = 0; mt < 2; mt++) {
            const int r = wm * 32 + mt * 16 + g;
#pragma unroll
            for (int nt = 0; nt < NT; nt++) {
                const int col = wn * (NS / 4) + nt * 8 + qk;
                *(float2*)&Ss[r * NSP + col] =
                    make_float2(acc[mt][nt][0] * scale, acc[mt][nt][1] * scale);
                *(float2*)&Ss[(r + 8) * NSP + col] =
                    make_float2(acc[mt][nt][2] * scale, acc[mt][nt][3] * scale);
            }
        }
    }
    __syncthreads();

    // stage V^T (overwrites Ks)
    for (int i = tid; i < 32 * NS; i += 512) {
        const int e = i >> LOG, s = i & (NS - 1);
        Vs[e * NSP + s] = vtp[(((size_t)(b * 4 + h)) * 32 + e) * NS + s];
    }

    // softmax: warp w -> rows w*8..w*8+7; pack p (hi,lo) in place
    {
        constexpr int JN = NS / 32;
#pragma unroll
        for (int i = 0; i < 8; i++) {
            const int r = w * 8 + i;
            float v[JN];
            float mx = -1e30f;
#pragma unroll
            for (int j = 0; j < JN; j++) {
                v[j] = Ss[r * NSP + lane + j * 32];
                mx = fmaxf(mx, v[j]);
            }
#pragma unroll
            for (int o = 16; o > 0; o >>= 1)
                mx = fmaxf(mx, __shfl_xor_sync(0xffffffffu, mx, o));
            float sum = 0.f;
#pragma unroll
            for (int j = 0; j < JN; j++) { v[j] = __expf(v[j] - mx); sum += v[j]; }
#pragma unroll
            for (int o = 16; o > 0; o >>= 1)
                sum += __shfl_xor_sync(0xffffffffu, sum, o);
#pragma unroll
            for (int j = 0; j < JN; j++)
                Sp[r * NSP + lane + j * 32] = pack_hilo(v[j]);
            if (lane == 0) rs[r] = sum;
        }
    }
    __syncthreads();

    // ---- phase 3: O = P V.  16 warps: 8m (16q) x 2n (16e) ----
    {
        const int wm = w & 7, wn = w >> 3;
        float acc[2][4];
#pragma unroll
        for (int nt = 0; nt < 2; nt++)
#pragma unroll
            for (int r = 0; r < 4; r++) acc[nt][r] = 0.f;

#pragma unroll 4
        for (int kc = 0; kc < NS / 16; kc++) {
            const int kb = kc * 16;
            const int row = wm * 16 + g;
            uint32_t ah[4], al[4];
            {
                uint2 p0 = *(const uint2*)&Sp[row * NSP + kb + qk];
                uint2 p1 = *(const uint2*)&Sp[(row + 8) * NSP + kb + qk];
                uint2 p2 = *(const uint2*)&Sp[row * NSP + kb + qk + 8];
                uint2 p3 = *(const uint2*)&Sp[(row + 8) * NSP + kb + qk + 8];
                ah[0] = __byte_perm(p0.x, p0.y, 0x5410);
                al[0] = __byte_perm(p0.x, p0.y, 0x7632);
                ah[1] = __byte_perm(p1.x, p1.y, 0x5410);
                al[1] = __byte_perm(p1.x, p1.y, 0x7632);
                ah[2] = __byte_perm(p2.x, p2.y, 0x5410);
                al[2] = __byte_perm(p2.x, p2.y, 0x7632);
                ah[3] = __byte_perm(p3.x, p3.y, 0x5410);
                al[3] = __byte_perm(p3.x, p3.y, 0x7632);
            }
#pragma unroll
            for (int nt = 0; nt < 2; nt++) {
                const int e = wn * 16 + nt * 8 + g;
                uint2 p0 = *(const uint2*)&Vs[e * NSP + kb + qk];
                uint2 p1 = *(const uint2*)&Vs[e * NSP + kb + qk + 8];
                uint32_t bh[2], bl[2];
                bh[0] = __byte_perm(p0.x, p0.y, 0x5410);
                bl[0] = __byte_perm(p0.x, p0.y, 0x7632);
                bh[1] = __byte_perm(p1.x, p1.y, 0x5410);
                bl[1] = __byte_perm(p1.x, p1.y, 0x7632);
                mma16816(acc[nt], ah, bh);
                mma16816(acc[nt], al, bh);
                mma16816(acc[nt], ah, bl);
            }
        }

        const int r0 = wm * 16 + g;
        const float inv0 = 1.0f / rs[r0];
        const float inv1 = 1.0f / rs[r0 + 8];
#pragma unroll
        for (int nt = 0; nt < 2; nt++) {
            const int col = ooff + h * 32 + wn * 16 + nt * 8 + qk;
            *(uint2*)&catp[((size_t)(b * 4096 + q0 + r0)) * 256 + col] =
                make_uint2(pack_hilo(acc[nt][0] * inv0), pack_hilo(acc[nt][1] * inv0));
            *(uint2*)&catp[((size_t)(b * 4096 + q0 + r0 + 8)) * 256 + col] =
                make_uint2(pack_hilo(acc[nt][2] * inv1), pack_hilo(acc[nt][3] * inv1));
        }
    }
}

// ---------------------------------------------------------------------------
// launch
// ---------------------------------------------------------------------------
extern "C" void kernel_launch(void* const* d_in, const int* in_sizes, int n_in,
                              void* d_out, int out_size)
{
    const float* x      = (const float*)d_in[0];
    const float* q_w    = (const float*)d_in[1];
    const float* kv1_w  = (const float*)d_in[2];
    const float* kv2_w  = (const float*)d_in[3];
    const float* proj_w = (const float*)d_in[4];
    const float* proj_b = (const float*)d_in[5];
    const float* sr1_w  = (const float*)d_in[6];
    const float* sr1_b  = (const float*)d_in[7];
    const float* sr2_w  = (const float*)d_in[8];
    const float* sr2_b  = (const float*)d_in[9];
    const float* ln1_g  = (const float*)d_in[10];
    const float* ln1_b  = (const float*)d_in[11];
    const float* ln2_g  = (const float*)d_in[12];
    const float* ln2_b  = (const float*)d_in[13];
    const float* lc1_w  = (const float*)d_in[14];
    const float* lc1_b  = (const float*)d_in[15];
    const float* lc2_w  = (const float*)d_in[16];
    const float* lc2_b  = (const float*)d_in[17];
    float* out = (float*)d_out;

    uint32_t *p_xp, *p_qp, *p_catp, *p_x1p, *p_x2p, *p_k1p, *p_k2p, *p_v1p, *p_v2p;
    float *p_kv1, *p_kv2;
    __nv_bfloat16 *p_qwh, *p_qwl, *p_k1wh, *p_k1wl, *p_k2wh, *p_k2wl, *p_pwh, *p_pwl;
    cudaGetSymbolAddress((void**)&p_xp,   g_xp);
    cudaGetSymbolAddress((void**)&p_qp,   g_qp);
    cudaGetSymbolAddress((void**)&p_catp, g_catp);
    cudaGetSymbolAddress((void**)&p_x1p,  g_x1p);
    cudaGetSymbolAddress((void**)&p_x2p,  g_x2p);
    cudaGetSymbolAddress((void**)&p_kv1,  g_kv1);
    cudaGetSymbolAddress((void**)&p_kv2,  g_kv2);
    cudaGetSymbolAddress((void**)&p_k1p,  g_k1p);
    cudaGetSymbolAddress((void**)&p_k2p,  g_k2p);
    cudaGetSymbolAddress((void**)&p_v1p,  g_v1p);
    cudaGetSymbolAddress((void**)&p_v2p,  g_v2p);
    cudaGetSymbolAddress((void**)&p_qwh,  g_qwh);
    cudaGetSymbolAddress((void**)&p_qwl,  g_qwl);
    cudaGetSymbolAddress((void**)&p_k1wh, g_k1wh);
    cudaGetSymbolAddress((void**)&p_k1wl, g_k1wl);
    cudaGetSymbolAddress((void**)&p_k2wh, g_k2wh);
    cudaGetSymbolAddress((void**)&p_k2wl, g_k2wl);
    cudaGetSymbolAddress((void**)&p_pwh,  g_pwh);
    cudaGetSymbolAddress((void**)&p_pwl,  g_pwl);

    const int smem_gemm = 3 * (128 * 40 * 4) + 2 * (3 * 256 * 40 * 2);  // 184,320
    const int smem_dw   = 80 * 257 * 4 + 128;
    const int smem_a1   = (128 * 34 + 256 * 34) * 4 + 128 * 258 * 4 + 128 * 4; // 184,832
    const int smem_a2   = (128 * 34 + 64 * 34) * 4 + 128 * 66 * 4 + 128 * 4;   //  60,416
    cudaFuncSetAttribute(gemm_all,  cudaFuncAttributeMaxDynamicSharedMemorySize, smem_gemm);
    cudaFuncSetAttribute(gemm_proj, cudaFuncAttributeMaxDynamicSharedMemorySize, smem_gemm);
    cudaFuncSetAttribute(dwconv_wsplit, cudaFuncAttributeMaxDynamicSharedMemorySize, smem_dw);
    cudaFuncSetAttribute(attn_mma<256>, cudaFuncAttributeMaxDynamicSharedMemorySize, smem_a1);
    cudaFuncSetAttribute(attn_mma<64>,  cudaFuncAttributeMaxDynamicSharedMemorySize, smem_a2);

    // 0: dwconv (+x pack) + weight split
    dwconv_wsplit<<<768, 512, smem_dw>>>(
        x, p_xp, sr1_w, sr1_b, ln1_g, ln1_b, sr2_w, sr2_b, ln2_g, ln2_b,
        p_x1p, p_x2p,
        q_w, kv1_w, kv2_w, proj_w,
        p_qwh, p_qwl, p_k1wh, p_k1wl, p_k2wh, p_k2wl, p_pwh, p_pwl);
    // 1: all projections (q + kv1 + kv2)
    gemm_all<<<276, 512, smem_gemm>>>(
        p_xp, p_x1p, p_x2p, p_qwh, p_qwl, p_k1wh, p_k1wl, p_k2wh, p_k2wl,
        p_qp, p_kv1, p_k1p, p_kv2, p_k2p);
    // 2: v local conv -> packed V^T
    vconv_fused<<<BATCH * 256 + BATCH * 64, 128>>>(
        p_kv1, lc1_w, lc1_b, p_v1p, p_kv2, lc2_w, lc2_b, p_v2p);
    // 3: attention branch 1 (PROFILED SLOT)
    attn_mma<256><<<dim3(32, 32), 512, smem_a1>>>(p_qp, p_k1p, p_v1p, p_catp, 0,   0);
    // 4: attention branch 2
    attn_mma<64 ><<<dim3(32, 32), 512, smem_a2>>>(p_qp, p_k2p, p_v2p, p_catp, 128, 128);
    // 5: output projection
    gemm_proj<<<256, 512, smem_gemm>>>(p_catp, p_pwh, p_pwl, proj_b, out);
}

// round 8
// speedup vs baseline: 1.2177x; 1.2177x over previous
#include <cuda_runtime.h>
#include <cuda_bf16.h>
#include <cstdint>

// Problem constants: B=8, H=W=64, N=4096, C=256, nh=8, nh2=4, hd=32, sr=8
#define BATCH 8
#define NTOK 4096
#define CH 256

// ---------------------------------------------------------------------------
// Scratch (device globals)
// ---------------------------------------------------------------------------
__device__ uint32_t g_xp  [(size_t)BATCH * NTOK * CH];   // x packed (hi,lo)
__device__ uint32_t g_qp  [(size_t)BATCH * NTOK * CH];   // q packed
__device__ uint32_t g_catp[(size_t)BATCH * NTOK * CH];   // cat packed
__device__ uint32_t g_x1p [BATCH * 256 * CH];
__device__ uint32_t g_x2p [BATCH * 64 * CH];
__device__ float    g_kv1 [BATCH * 256 * CH];
__device__ float    g_kv2 [BATCH * 64 * CH];
__device__ uint32_t g_k1p [BATCH * 256 * 128];
__device__ uint32_t g_k2p [BATCH * 64 * 128];
__device__ uint32_t g_v1p [BATCH * 4 * 32 * 256];        // V^T packed [b,h][e][s]
__device__ uint32_t g_v2p [BATCH * 4 * 32 * 64];
// weight splits
__device__ __nv_bfloat16 g_qwh [256 * 256], g_qwl [256 * 256];
__device__ __nv_bfloat16 g_k1wh[256 * 256], g_k1wl[256 * 256];
__device__ __nv_bfloat16 g_k2wh[256 * 256], g_k2wl[256 * 256];
__device__ __nv_bfloat16 g_pwh [256 * 256], g_pwl [256 * 256];

// ---------------------------------------------------------------------------
// helpers
// ---------------------------------------------------------------------------
__device__ __forceinline__ uint32_t pack_hilo(float v) {
    __nv_bfloat16 h = __float2bfloat16(v);
    __nv_bfloat16 l = __float2bfloat16(v - __bfloat162float(h));
    return (uint32_t)__bfloat16_as_ushort(h) |
           ((uint32_t)__bfloat16_as_ushort(l) << 16);
}

// Pack two fp32 into bf16x2 hi-pair and residual lo-pair (elem0 in low half).
__device__ __forceinline__ void pack2_hilo(
    float p0, float p1, uint32_t& h, uint32_t& l)
{
    uint32_t hp;
    asm("cvt.rn.bf16x2.f32 %0, %1, %2;" : "=r"(hp) : "f"(p1), "f"(p0));
    const float r0 = p0 - __uint_as_float(hp << 16);
    const float r1 = p1 - __uint_as_float(hp & 0xffff0000u);
    uint32_t lp;
    asm("cvt.rn.bf16x2.f32 %0, %1, %2;" : "=r"(lp) : "f"(r1), "f"(r0));
    h = hp; l = lp;
}

__device__ __forceinline__ void mma16816(
    float* c, const uint32_t* a, const uint32_t* b)
{
    asm volatile(
        "mma.sync.aligned.m16n8k16.row.col.f32.bf16.bf16.f32 "
        "{%0,%1,%2,%3}, {%4,%5,%6,%7}, {%8,%9}, {%0,%1,%2,%3};"
        : "+f"(c[0]), "+f"(c[1]), "+f"(c[2]), "+f"(c[3])
        : "r"(a[0]), "r"(a[1]), "r"(a[2]), "r"(a[3]), "r"(b[0]), "r"(b[1]));
}

__device__ __forceinline__ void cpa16(void* dst, const void* src) {
    uint32_t d = (uint32_t)__cvta_generic_to_shared(dst);
    asm volatile("cp.async.cg.shared.global [%0], [%1], 16;\n"
                 :: "r"(d), "l"(src));
}

// ---------------------------------------------------------------------------
// Pipelined tensor-core GEMM body (verified). K=256, N=256.
// ---------------------------------------------------------------------------
template<int MODE>
__device__ __forceinline__ void gemm_body(
    const uint32_t* __restrict__ A,
    const __nv_bfloat16* __restrict__ Wh,
    const __nv_bfloat16* __restrict__ Wl,
    const float* __restrict__ bias,
    float* __restrict__ Cf, uint32_t* __restrict__ Cp,
    int m0, char* smraw)
{
    constexpr int LDA = 40;
    constexpr int LDB = 40;
    constexpr int ASZ = 128 * LDA;
    constexpr int BSZ = 256 * LDB;

    uint32_t*      Ap = (uint32_t*)smraw;
    __nv_bfloat16* Bh = (__nv_bfloat16*)(Ap + 3 * ASZ);
    __nv_bfloat16* Bl = Bh + 3 * BSZ;

    const int tid = threadIdx.x;
    const int w = tid >> 5, lane = tid & 31;
    const int wm = w & 3, wn = w >> 2;
    const int g = lane >> 2, qk = (lane & 3) * 2;

    auto load_stage = [&](int s, int k0) {
#pragma unroll
        for (int i = 0; i < 2; i++) {
            const int c = tid + i * 512;
            const int row = c >> 3, ch = c & 7;
            cpa16(&Ap[s * ASZ + row * LDA + ch * 4],
                  &A[(size_t)(m0 + row) * 256 + k0 + ch * 4]);
        }
#pragma unroll
        for (int i = 0; i < 2; i++) {
            const int c = tid + i * 512;
            const int row = c >> 2, ch = c & 3;
            cpa16(&Bh[s * BSZ + row * LDB + ch * 8],
                  &Wh[(size_t)row * 256 + k0 + ch * 8]);
        }
#pragma unroll
        for (int i = 0; i < 2; i++) {
            const int c = tid + i * 512;
            const int row = c >> 2, ch = c & 3;
            cpa16(&Bl[s * BSZ + row * LDB + ch * 8],
                  &Wl[(size_t)row * 256 + k0 + ch * 8]);
        }
        asm volatile("cp.async.commit_group;\n" ::: "memory");
    };

    float acc[2][8][4];
#pragma unroll
    for (int mt = 0; mt < 2; mt++)
#pragma unroll
        for (int nt = 0; nt < 8; nt++)
#pragma unroll
            for (int r = 0; r < 4; r++) acc[mt][nt][r] = 0.f;

    load_stage(0, 0);
    load_stage(1, 32);

    for (int it = 0; it < 8; it++) {
        if (it < 7) asm volatile("cp.async.wait_group 1;\n" ::: "memory");
        else        asm volatile("cp.async.wait_group 0;\n" ::: "memory");
        __syncthreads();
        if (it + 2 < 8) load_stage((it + 2) % 3, (it + 2) * 32);

        const int s = it % 3;
        const uint32_t*      As  = Ap + s * ASZ;
        const __nv_bfloat16* Bhs = Bh + s * BSZ;
        const __nv_bfloat16* Bls = Bl + s * BSZ;

#pragma unroll
        for (int ks = 0; ks < 2; ks++) {
            const int kb = ks * 16;
            uint32_t ah[2][4], al[2][4];
#pragma unroll
            for (int mt = 0; mt < 2; mt++) {
                const int row = wm * 32 + mt * 16 + g;
                uint2 p0 = *(const uint2*)&As[row * LDA + kb + qk];
                uint2 p1 = *(const uint2*)&As[(row + 8) * LDA + kb + qk];
                uint2 p2 = *(const uint2*)&As[row * LDA + kb + qk + 8];
                uint2 p3 = *(const uint2*)&As[(row + 8) * LDA + kb + qk + 8];
                ah[mt][0] = __byte_perm(p0.x, p0.y, 0x5410);
                al[mt][0] = __byte_perm(p0.x, p0.y, 0x7632);
                ah[mt][1] = __byte_perm(p1.x, p1.y, 0x5410);
                al[mt][1] = __byte_perm(p1.x, p1.y, 0x7632);
                ah[mt][2] = __byte_perm(p2.x, p2.y, 0x5410);
                al[mt][2] = __byte_perm(p2.x, p2.y, 0x7632);
                ah[mt][3] = __byte_perm(p3.x, p3.y, 0x5410);
                al[mt][3] = __byte_perm(p3.x, p3.y, 0x7632);
            }
            uint32_t bf[8][2];
#pragma unroll
            for (int nt = 0; nt < 8; nt++) {
                const __nv_bfloat16* pb = &Bhs[(wn * 64 + nt * 8 + g) * LDB + kb + qk];
                bf[nt][0] = *(const uint32_t*)pb;
                bf[nt][1] = *(const uint32_t*)(pb + 8);
            }
#pragma unroll
            for (int mt = 0; mt < 2; mt++)
#pragma unroll
                for (int nt = 0; nt < 8; nt++) {
                    mma16816(acc[mt][nt], ah[mt], bf[nt]);
                    mma16816(acc[mt][nt], al[mt], bf[nt]);
                }
#pragma unroll
            for (int nt = 0; nt < 8; nt++) {
                const __nv_bfloat16* pb = &Bls[(wn * 64 + nt * 8 + g) * LDB + kb + qk];
                bf[nt][0] = *(const uint32_t*)pb;
                bf[nt][1] = *(const uint32_t*)(pb + 8);
            }
#pragma unroll
            for (int mt = 0; mt < 2; mt++)
#pragma unroll
                for (int nt = 0; nt < 8; nt++)
                    mma16816(acc[mt][nt], ah[mt], bf[nt]);
        }
        __syncthreads();
    }

#pragma unroll
    for (int mt = 0; mt < 2; mt++) {
        const int r = m0 + wm * 32 + mt * 16 + g;
#pragma unroll
        for (int nt = 0; nt < 8; nt++) {
            const int col = wn * 64 + nt * 8 + qk;
            if constexpr (MODE == 0) {
                const float b0 = bias[col], b1 = bias[col + 1];
                *(float2*)&Cf[(size_t)r * 256 + col] =
                    make_float2(acc[mt][nt][0] + b0, acc[mt][nt][1] + b1);
                *(float2*)&Cf[(size_t)(r + 8) * 256 + col] =
                    make_float2(acc[mt][nt][2] + b0, acc[mt][nt][3] + b1);
            } else if constexpr (MODE == 1) {
                *(uint2*)&Cp[(size_t)r * 256 + col] =
                    make_uint2(pack_hilo(acc[mt][nt][0]), pack_hilo(acc[mt][nt][1]));
                *(uint2*)&Cp[(size_t)(r + 8) * 256 + col] =
                    make_uint2(pack_hilo(acc[mt][nt][2]), pack_hilo(acc[mt][nt][3]));
            } else {
                *(float2*)&Cf[(size_t)r * 256 + col] =
                    make_float2(acc[mt][nt][0], acc[mt][nt][1]);
                *(float2*)&Cf[(size_t)(r + 8) * 256 + col] =
                    make_float2(acc[mt][nt][2], acc[mt][nt][3]);
                if (col < 128) {
                    *(uint2*)&Cp[(size_t)r * 128 + col] =
                        make_uint2(pack_hilo(acc[mt][nt][0]), pack_hilo(acc[mt][nt][1]));
                    *(uint2*)&Cp[(size_t)(r + 8) * 128 + col] =
                        make_uint2(pack_hilo(acc[mt][nt][2]), pack_hilo(acc[mt][nt][3]));
                }
            }
        }
    }
}

// Combined projection GEMMs: q (256 blocks) + kv1 (16) + kv2 (4).
__global__ __launch_bounds__(512) void gemm_all(
    const uint32_t* __restrict__ xp,
    const uint32_t* __restrict__ x1p, const uint32_t* __restrict__ x2p,
    const __nv_bfloat16* __restrict__ qwh, const __nv_bfloat16* __restrict__ qwl,
    const __nv_bfloat16* __restrict__ k1wh, const __nv_bfloat16* __restrict__ k1wl,
    const __nv_bfloat16* __restrict__ k2wh, const __nv_bfloat16* __restrict__ k2wl,
    uint32_t* __restrict__ qp,
    float* __restrict__ kv1, uint32_t* __restrict__ k1p,
    float* __restrict__ kv2, uint32_t* __restrict__ k2p)
{
    extern __shared__ __align__(16) char smraw[];
    if (blockIdx.x < 256)
        gemm_body<1>(xp, qwh, qwl, nullptr, nullptr, qp, blockIdx.x * 128, smraw);
    else if (blockIdx.x < 272)
        gemm_body<2>(x1p, k1wh, k1wl, nullptr, kv1, k1p, (blockIdx.x - 256) * 128, smraw);
    else
        gemm_body<2>(x2p, k2wh, k2wl, nullptr, kv2, k2p, (blockIdx.x - 272) * 128, smraw);
}

// Output projection.
__global__ __launch_bounds__(512) void gemm_proj(
    const uint32_t* __restrict__ A,
    const __nv_bfloat16* __restrict__ Wh, const __nv_bfloat16* __restrict__ Wl,
    const float* __restrict__ bias, float* __restrict__ Cf)
{
    extern __shared__ __align__(16) char smraw[];
    gemm_body<0>(A, Wh, Wl, bias, Cf, nullptr, blockIdx.x * 128, smraw);
}

// ---------------------------------------------------------------------------
// LN + exact GELU block helper (per 256-thread window group)
// ---------------------------------------------------------------------------
__device__ __forceinline__ float ln_gelu_block(
    float a, const float* __restrict__ g, const float* __restrict__ bln,
    float* red, int c)
{
    float s1 = a, s2 = a * a;
#pragma unroll
    for (int o = 16; o > 0; o >>= 1) {
        s1 += __shfl_xor_sync(0xffffffffu, s1, o);
        s2 += __shfl_xor_sync(0xffffffffu, s2, o);
    }
    if ((c & 31) == 0) { red[c >> 5] = s1; red[8 + (c >> 5)] = s2; }
    __syncthreads();
    if (c == 0) {
        float a0 = 0.f, b0 = 0.f;
#pragma unroll
        for (int i = 0; i < 8; i++) { a0 += red[i]; b0 += red[8 + i]; }
        red[0] = a0; red[8] = b0;
    }
    __syncthreads();
    const float mean = red[0] * (1.f / 256.f);
    const float var  = red[8] * (1.f / 256.f) - mean * mean;
    float y = (a - mean) * rsqrtf(var + 1e-5f) * g[c] + bln[c];
    y = 0.5f * y * (1.0f + erff(y * 0.70710678118654752f));
    __syncthreads();
    return y;
}

// ---------------------------------------------------------------------------
// dwconv_fused + x-pack + weight split (unchanged, verified)
// ---------------------------------------------------------------------------
__global__ __launch_bounds__(512) void dwconv_wsplit(
    const float* __restrict__ x, uint32_t* __restrict__ xp,
    const float* __restrict__ w1, const float* __restrict__ b1c,
    const float* __restrict__ g1, const float* __restrict__ bl1,
    const float* __restrict__ w2, const float* __restrict__ b2c,
    const float* __restrict__ g2, const float* __restrict__ bl2,
    uint32_t* __restrict__ x1p, uint32_t* __restrict__ x2p,
    const float* __restrict__ w0m, const float* __restrict__ w1m,
    const float* __restrict__ w2m, const float* __restrict__ w3m,
    __nv_bfloat16* __restrict__ h0, __nv_bfloat16* __restrict__ l0,
    __nv_bfloat16* __restrict__ h1, __nv_bfloat16* __restrict__ l1,
    __nv_bfloat16* __restrict__ h2, __nv_bfloat16* __restrict__ l2,
    __nv_bfloat16* __restrict__ h3, __nv_bfloat16* __restrict__ l3)
{
    if (blockIdx.x >= 256) {
        const int widx = blockIdx.x - 256;
        const int which = widx >> 7;
        const int i = (widx & 127) * 512 + threadIdx.x;
        const float* in = which == 0 ? w0m : which == 1 ? w1m : which == 2 ? w2m : w3m;
        __nv_bfloat16* oh = which == 0 ? h0 : which == 1 ? h1 : which == 2 ? h2 : h3;
        __nv_bfloat16* ol = which == 0 ? l0 : which == 1 ? l1 : which == 2 ? l2 : l3;
        const float v = in[i];
        const __nv_bfloat16 hi = __float2bfloat16(v);
        oh[i] = hi;
        ol[i] = __float2bfloat16(v - __bfloat162float(hi));
        return;
    }

    extern __shared__ float sw[];
    float* w2s = sw;
    float* w1s = sw + 64 * 257;
    float* redb = sw + 80 * 257;

    const int tid = threadIdx.x;
    const int c = tid & 255;
    const int win = tid >> 8;
    float* red = redb + win * 16;

    const int b = blockIdx.x >> 5;
    const int pair = blockIdx.x & 31;
    const int t2 = pair * 2 + win;
    const int oh2 = t2 >> 3, ow2 = t2 & 7;

    for (int i = tid; i < 64 * 256; i += 512)
        w2s[(i & 63) * 257 + (i >> 6)] = w2[i];
    for (int i = tid; i < 16 * 256; i += 512)
        w1s[(i & 15) * 257 + (i >> 4)] = w1[i];
    __syncthreads();

    float acc2 = b2c[c];
    float acc1[2][2];
    acc1[0][0] = acc1[0][1] = acc1[1][0] = acc1[1][1] = b1c[c];

#pragma unroll
    for (int kh = 0; kh < 8; kh++) {
#pragma unroll
        for (int kw = 0; kw < 8; kw++) {
            const int ih = oh2 * 8 + kh, iw = ow2 * 8 + kw;
            const size_t xi = ((size_t)b * NTOK + ih * 64 + iw) * CH + c;
            const float xv = x[xi];
            xp[xi] = pack_hilo(xv);
            acc2 += xv * w2s[(kh * 8 + kw) * 257 + c];
            acc1[kh >> 2][kw >> 2] += xv * w1s[((kh & 3) * 4 + (kw & 3)) * 257 + c];
        }
    }

    const float y2 = ln_gelu_block(acc2, g2, bl2, red, c);
    x2p[((size_t)b * 64 + t2) * CH + c] = pack_hilo(y2);
#pragma unroll
    for (int i = 0; i < 2; i++)
#pragma unroll
        for (int j = 0; j < 2; j++) {
            const float y1 = ln_gelu_block(acc1[i][j], g1, bl1, red, c);
            const int t1 = (oh2 * 2 + i) * 16 + (ow2 * 2 + j);
            x1p[((size_t)b * 256 + t1) * CH + c] = pack_hilo(y1);
        }
}

// ---------------------------------------------------------------------------
// Fused v local conv (+residual) -> packed V^T [b,h][e][s] (unchanged)
// ---------------------------------------------------------------------------
__global__ __launch_bounds__(128) void vconv_fused(
    const float* __restrict__ kv1, const float* __restrict__ lcw1,
    const float* __restrict__ lcb1, uint32_t* __restrict__ v1p,
    const float* __restrict__ kv2, const float* __restrict__ lcw2,
    const float* __restrict__ lcb2, uint32_t* __restrict__ v2p)
{
    int token, HS;
    const float *kv, *lcw, *lcb;
    uint32_t* vtp;
    if (blockIdx.x < BATCH * 256) {
        token = blockIdx.x; HS = 16; kv = kv1; lcw = lcw1; lcb = lcb1; vtp = v1p;
    } else {
        token = blockIdx.x - BATCH * 256; HS = 8; kv = kv2; lcw = lcw2; lcb = lcb2; vtp = v2p;
    }
    const int NS = HS * HS;
    const int b  = token / NS;
    const int s  = token - b * NS;
    const int hs = s / HS, ws = s - hs * HS;
    const int c  = threadIdx.x;

    float acc = lcb[c];
#pragma unroll
    for (int kh = 0; kh < 3; kh++)
#pragma unroll
        for (int kw = 0; kw < 3; kw++) {
            const int ih = hs - 1 + kh, iw = ws - 1 + kw;
            if (ih >= 0 && ih < HS && iw >= 0 && iw < HS)
                acc += kv[((size_t)b * NS + ih * HS + iw) * 256 + 128 + c]
                     * lcw[c * 9 + kh * 3 + kw];
        }
    const float v = kv[(size_t)token * 256 + 128 + c] + acc;
    const int h = c >> 5, e = c & 31;
    vtp[(((size_t)b * 4 + h) * 32 + e) * NS + s] = pack_hilo(v);
}

// ---------------------------------------------------------------------------
// Flash-style attention: S and P live in registers; softmax via shuffles +
// small smem stats; phase-3 A-operand built from registers (zero LDS);
// V read without cross-warp redundancy; partial-O reduced via smem.
// 16 warps = 4 m-groups (32 q) x 4 s-chunks (NS/4).
// ---------------------------------------------------------------------------
template<int NS>
__global__ __launch_bounds__(512) void attn_flash(
    const uint32_t* __restrict__ qp,
    const uint32_t* __restrict__ kp,
    const uint32_t* __restrict__ vtp,
    uint32_t* __restrict__ catp,
    int qoff, int ooff)
{
    constexpr int SCH = NS / 4;        // s per warp chunk
    constexpr int NT2 = SCH / 8;       // n8 tiles per warp (phase 1)
    constexpr int KT  = SCH / 16;      // k16 tiles per warp (phase 3)
    constexpr int LDQ = 34;
    constexpr int NSP = NS + 2;
    constexpr int LOG = (NS == 256) ? 8 : 6;
    // smem word offsets
    constexpr int OFF_KS = 128 * LDQ;
    constexpr int KS_END = OFF_KS + NS * LDQ;
    constexpr int VS_END = 32 * NSP;
    constexpr int OFF_PB = (KS_END > VS_END) ? KS_END : VS_END;
    constexpr int OFF_MX = OFF_PB + 16 * 32 * 34;
    constexpr int OFF_SM = OFF_MX + 512;
    const float kfac = 0.17677669529663689f * 1.4426950408889634f;

    extern __shared__ float smf[];
    uint32_t* SM  = (uint32_t*)smf;
    uint32_t* Qs  = SM;                 // [128][LDQ]  (dead after phase 1)
    uint32_t* Ks  = SM + OFF_KS;        // [NS][LDQ]   (dead after phase 1)
    uint32_t* Vs  = SM;                 // [32][NSP]   (aliases Qs/Ks head)
    float*    pb  = smf + OFF_PB;       // [16][32][34] partial O
    float*    mx  = smf + OFF_MX;       // [4][128] chunk maxima
    float*    smr = smf + OFF_SM;       // [4][128] chunk sums

    const int b = blockIdx.x >> 2, h = blockIdx.x & 3;
    const int q0 = blockIdx.y * 128;
    const int tid = threadIdx.x, lane = tid & 31, w = tid >> 5;
    const int g = lane >> 2, qk = (lane & 3) * 2;
    const int wm = w >> 2, wn = w & 3;

    // stage Q (128x32) and K (NSx32)
    for (int i = tid; i < 128 * 32; i += 512) {
        const int r = i >> 5, e = i & 31;
        Qs[r * LDQ + e] = qp[((size_t)(b * 4096 + q0 + r)) * 256 + qoff + h * 32 + e];
    }
    for (int i = tid; i < NS * 32; i += 512) {
        const int s = i >> 5, e = i & 31;
        Ks[s * LDQ + e] = kp[((size_t)(b * NS + s)) * 128 + h * 32 + e];
    }
    __syncthreads();

    // ---- phase 1: S = Q K^T into registers ----
    float acc[2][NT2][4];
#pragma unroll
    for (int mt = 0; mt < 2; mt++)
#pragma unroll
        for (int nt = 0; nt < NT2; nt++)
#pragma unroll
            for (int r = 0; r < 4; r++) acc[mt][nt][r] = 0.f;

#pragma unroll
    for (int kc = 0; kc < 2; kc++) {
        const int kb = kc * 16;
        uint32_t ah[2][4], al[2][4];
#pragma unroll
        for (int mt = 0; mt < 2; mt++) {
            const int row = wm * 32 + mt * 16 + g;
            uint2 p0 = *(const uint2*)&Qs[row * LDQ + kb + qk];
            uint2 p1 = *(const uint2*)&Qs[(row + 8) * LDQ + kb + qk];
            uint2 p2 = *(const uint2*)&Qs[row * LDQ + kb + qk + 8];
            uint2 p3 = *(const uint2*)&Qs[(row + 8) * LDQ + kb + qk + 8];
            ah[mt][0] = __byte_perm(p0.x, p0.y, 0x5410);
            al[mt][0] = __byte_perm(p0.x, p0.y, 0x7632);
            ah[mt][1] = __byte_perm(p1.x, p1.y, 0x5410);
            al[mt][1] = __byte_perm(p1.x, p1.y, 0x7632);
            ah[mt][2] = __byte_perm(p2.x, p2.y, 0x5410);
            al[mt][2] = __byte_perm(p2.x, p2.y, 0x7632);
            ah[mt][3] = __byte_perm(p3.x, p3.y, 0x5410);
            al[mt][3] = __byte_perm(p3.x, p3.y, 0x7632);
        }
#pragma unroll
        for (int nt = 0; nt < NT2; nt++) {
            const int srow = wn * SCH + nt * 8 + g;
            uint2 p0 = *(const uint2*)&Ks[srow * LDQ + kb + qk];
            uint2 p1 = *(const uint2*)&Ks[srow * LDQ + kb + qk + 8];
            uint32_t bh[2], bl[2];
            bh[0] = __byte_perm(p0.x, p0.y, 0x5410);
            bl[0] = __byte_perm(p0.x, p0.y, 0x7632);
            bh[1] = __byte_perm(p1.x, p1.y, 0x5410);
            bl[1] = __byte_perm(p1.x, p1.y, 0x7632);
#pragma unroll
            for (int mt = 0; mt < 2; mt++) {
                mma16816(acc[mt][nt], ah[mt], bh);
                mma16816(acc[mt][nt], al[mt], bh);
                mma16816(acc[mt][nt], ah[mt], bl);
            }
        }
    }

    // ---- chunk max (registers -> shuffles -> smem) ----
#pragma unroll
    for (int mt = 0; mt < 2; mt++)
#pragma unroll
        for (int half = 0; half < 2; half++) {
            float m = acc[mt][0][half * 2];
#pragma unroll
            for (int nt = 0; nt < NT2; nt++) {
                m = fmaxf(m, acc[mt][nt][half * 2]);
                m = fmaxf(m, acc[mt][nt][half * 2 + 1]);
            }
            m = fmaxf(m, __shfl_xor_sync(0xffffffffu, m, 1));
            m = fmaxf(m, __shfl_xor_sync(0xffffffffu, m, 2));
            if ((lane & 3) == 0)
                mx[wn * 128 + wm * 32 + mt * 16 + half * 8 + g] = m;
        }
    __syncthreads();   // barrier 1: Q/K reads done, maxima visible

    // stage V^T (overwrites Qs/Ks region)
    for (int i = tid; i < 32 * NS; i += 512) {
        const int e = i >> LOG, s = i & (NS - 1);
        Vs[e * NSP + s] = vtp[(((size_t)(b * 4 + h)) * 32 + e) * NS + s];
    }

    // ---- global max, exp in registers, chunk sums ----
#pragma unroll
    for (int mt = 0; mt < 2; mt++)
#pragma unroll
        for (int half = 0; half < 2; half++) {
            const int row = wm * 32 + mt * 16 + half * 8 + g;
            float m = fmaxf(fmaxf(mx[row], mx[128 + row]),
                            fmaxf(mx[256 + row], mx[384 + row]));
            float s = 0.f;
#pragma unroll
            for (int nt = 0; nt < NT2; nt++) {
                float e0 = exp2f((acc[mt][nt][half * 2]     - m) * kfac);
                float e1 = exp2f((acc[mt][nt][half * 2 + 1] - m) * kfac);
                acc[mt][nt][half * 2]     = e0;
                acc[mt][nt][half * 2 + 1] = e1;
                s += e0 + e1;
            }
            s += __shfl_xor_sync(0xffffffffu, s, 1);
            s += __shfl_xor_sync(0xffffffffu, s, 2);
            if ((lane & 3) == 0) smr[wn * 128 + row] = s;
        }
    __syncthreads();   // barrier 2: V staged, sums visible

    // ---- phase 3: O_partial = P V over this warp's s-chunk ----
    float acc3[2][4][4];
#pragma unroll
    for (int mt = 0; mt < 2; mt++)
#pragma unroll
        for (int nt = 0; nt < 4; nt++)
#pragma unroll
            for (int r = 0; r < 4; r++) acc3[mt][nt][r] = 0.f;

#pragma unroll
    for (int kt = 0; kt < KT; kt++) {
        uint32_t bh[4][2], bl[4][2];
#pragma unroll
        for (int nt3 = 0; nt3 < 4; nt3++) {
            const int e = nt3 * 8 + g;
            const int base = e * NSP + wn * SCH + kt * 16 + qk;
            uint2 p0 = *(const uint2*)&Vs[base];
            uint2 p1 = *(const uint2*)&Vs[base + 8];
            bh[nt3][0] = __byte_perm(p0.x, p0.y, 0x5410);
            bl[nt3][0] = __byte_perm(p0.x, p0.y, 0x7632);
            bh[nt3][1] = __byte_perm(p1.x, p1.y, 0x5410);
            bl[nt3][1] = __byte_perm(p1.x, p1.y, 0x7632);
        }
#pragma unroll
        for (int mt = 0; mt < 2; mt++) {
            uint32_t ah[4], al[4];
            pack2_hilo(acc[mt][2 * kt][0],     acc[mt][2 * kt][1],     ah[0], al[0]);
            pack2_hilo(acc[mt][2 * kt][2],     acc[mt][2 * kt][3],     ah[1], al[1]);
            pack2_hilo(acc[mt][2 * kt + 1][0], acc[mt][2 * kt + 1][1], ah[2], al[2]);
            pack2_hilo(acc[mt][2 * kt + 1][2], acc[mt][2 * kt + 1][3], ah[3], al[3]);
#pragma unroll
            for (int nt3 = 0; nt3 < 4; nt3++) {
                mma16816(acc3[mt][nt3], ah, bh[nt3]);
                mma16816(acc3[mt][nt3], al, bh[nt3]);
                mma16816(acc3[mt][nt3], ah, bl[nt3]);
            }
        }
    }

    // write partials (fragment layout)
#pragma unroll
    for (int mt = 0; mt < 2; mt++)
#pragma unroll
        for (int nt3 = 0; nt3 < 4; nt3++) {
            const int rl = mt * 16 + g;
            const int base = ((wn * 4 + wm) * 32 + rl) * 34 + nt3 * 8 + qk;
            *(float2*)&pb[base] = make_float2(acc3[mt][nt3][0], acc3[mt][nt3][1]);
            *(float2*)&pb[base + 8 * 34] = make_float2(acc3[mt][nt3][2], acc3[mt][nt3][3]);
        }
    __syncthreads();   // barrier 3: partials visible

    // ---- reduction + epilogue: warp (wm, wn) -> rows wm*32..+32, e = wn*8..+8
#pragma unroll
    for (int rr = 0; rr < 4; rr++) {
        const int rloc = rr * 8 + (lane >> 2);
        const int row = wm * 32 + rloc;
        const int cl = wn * 8 + (lane & 3) * 2;
        float ox = 0.f, oy = 0.f;
#pragma unroll
        for (int wv = 0; wv < 4; wv++) {
            float2 p = *(const float2*)&pb[((wv * 4 + wm) * 32 + rloc) * 34 + cl];
            ox += p.x; oy += p.y;
        }
        const float inv = 1.0f / (smr[row] + smr[128 + row] +
                                  smr[256 + row] + smr[384 + row]);
        const int col = ooff + h * 32 + cl;
        *(uint2*)&catp[((size_t)(b * 4096 + q0 + row)) * 256 + col] =
            make_uint2(pack_hilo(ox * inv), pack_hilo(oy * inv));
    }
}

// ---------------------------------------------------------------------------
// launch
// ---------------------------------------------------------------------------
extern "C" void kernel_launch(void* const* d_in, const int* in_sizes, int n_in,
                              void* d_out, int out_size)
{
    const float* x      = (const float*)d_in[0];
    const float* q_w    = (const float*)d_in[1];
    const float* kv1_w  = (const float*)d_in[2];
    const float* kv2_w  = (const float*)d_in[3];
    const float* proj_w = (const float*)d_in[4];
    const float* proj_b = (const float*)d_in[5];
    const float* sr1_w  = (const float*)d_in[6];
    const float* sr1_b  = (const float*)d_in[7];
    const float* sr2_w  = (const float*)d_in[8];
    const float* sr2_b  = (const float*)d_in[9];
    const float* ln1_g  = (const float*)d_in[10];
    const float* ln1_b  = (const float*)d_in[11];
    const float* ln2_g  = (const float*)d_in[12];
    const float* ln2_b  = (const float*)d_in[13];
    const float* lc1_w  = (const float*)d_in[14];
    const float* lc1_b  = (const float*)d_in[15];
    const float* lc2_w  = (const float*)d_in[16];
    const float* lc2_b  = (const float*)d_in[17];
    float* out = (float*)d_out;

    uint32_t *p_xp, *p_qp, *p_catp, *p_x1p, *p_x2p, *p_k1p, *p_k2p, *p_v1p, *p_v2p;
    float *p_kv1, *p_kv2;
    __nv_bfloat16 *p_qwh, *p_qwl, *p_k1wh, *p_k1wl, *p_k2wh, *p_k2wl, *p_pwh, *p_pwl;
    cudaGetSymbolAddress((void**)&p_xp,   g_xp);
    cudaGetSymbolAddress((void**)&p_qp,   g_qp);
    cudaGetSymbolAddress((void**)&p_catp, g_catp);
    cudaGetSymbolAddress((void**)&p_x1p,  g_x1p);
    cudaGetSymbolAddress((void**)&p_x2p,  g_x2p);
    cudaGetSymbolAddress((void**)&p_kv1,  g_kv1);
    cudaGetSymbolAddress((void**)&p_kv2,  g_kv2);
    cudaGetSymbolAddress((void**)&p_k1p,  g_k1p);
    cudaGetSymbolAddress((void**)&p_k2p,  g_k2p);
    cudaGetSymbolAddress((void**)&p_v1p,  g_v1p);
    cudaGetSymbolAddress((void**)&p_v2p,  g_v2p);
    cudaGetSymbolAddress((void**)&p_qwh,  g_qwh);
    cudaGetSymbolAddress((void**)&p_qwl,  g_qwl);
    cudaGetSymbolAddress((void**)&p_k1wh, g_k1wh);
    cudaGetSymbolAddress((void**)&p_k1wl, g_k1wl);
    cudaGetSymbolAddress((void**)&p_k2wh, g_k2wh);
    cudaGetSymbolAddress((void**)&p_k2wl, g_k2wl);
    cudaGetSymbolAddress((void**)&p_pwh,  g_pwh);
    cudaGetSymbolAddress((void**)&p_pwl,  g_pwl);

    const int smem_gemm = 3 * (128 * 40 * 4) + 2 * (3 * 256 * 40 * 2);  // 184,320
    const int smem_dw   = 80 * 257 * 4 + 128;
    // attn_flash smem (bytes): (max(128*34 + NS*34, 32*(NS+2)) + 16*32*34 + 1024) * 4
    const int smem_a1 = ((128 * 34 + 256 * 34) + 16 * 32 * 34 + 1024) * 4;  // 125,952
    const int smem_a2 = ((128 * 34 + 64 * 34) + 16 * 32 * 34 + 1024) * 4;   //  99,840
    cudaFuncSetAttribute(gemm_all,  cudaFuncAttributeMaxDynamicSharedMemorySize, smem_gemm);
    cudaFuncSetAttribute(gemm_proj, cudaFuncAttributeMaxDynamicSharedMemorySize, smem_gemm);
    cudaFuncSetAttribute(dwconv_wsplit, cudaFuncAttributeMaxDynamicSharedMemorySize, smem_dw);
    cudaFuncSetAttribute(attn_flash<256>, cudaFuncAttributeMaxDynamicSharedMemorySize, smem_a1);
    cudaFuncSetAttribute(attn_flash<64>,  cudaFuncAttributeMaxDynamicSharedMemorySize, smem_a2);

    // 0: dwconv (+x pack) + weight split
    dwconv_wsplit<<<768, 512, smem_dw>>>(
        x, p_xp, sr1_w, sr1_b, ln1_g, ln1_b, sr2_w, sr2_b, ln2_g, ln2_b,
        p_x1p, p_x2p,
        q_w, kv1_w, kv2_w, proj_w,
        p_qwh, p_qwl, p_k1wh, p_k1wl, p_k2wh, p_k2wl, p_pwh, p_pwl);
    // 1: all projections (q + kv1 + kv2)
    gemm_all<<<276, 512, smem_gemm>>>(
        p_xp, p_x1p, p_x2p, p_qwh, p_qwl, p_k1wh, p_k1wl, p_k2wh, p_k2wl,
        p_qp, p_kv1, p_k1p, p_kv2, p_k2p);
    // 2: v local conv -> packed V^T
    vconv_fused<<<BATCH * 256 + BATCH * 64, 128>>>(
        p_kv1, lc1_w, lc1_b, p_v1p, p_kv2, lc2_w, lc2_b, p_v2p);
    // 3: attention branch 1 (PROFILED SLOT)
    attn_flash<256><<<dim3(32, 32), 512, smem_a1>>>(p_qp, p_k1p, p_v1p, p_catp, 0,   0);
    // 4: attention branch 2
    attn_flash<64 ><<<dim3(32, 32), 512, smem_a2>>>(p_qp, p_k2p, p_v2p, p_catp, 128, 128);
    // 5: output projection
    gemm_proj<<<256, 512, smem_gemm>>>(p_catp, p_pwh, p_pwl, proj_b, out);
}

// round 9
// speedup vs baseline: 1.6813x; 1.3807x over previous
#include <cuda_runtime.h>
#include <cuda_bf16.h>
#include <cstdint>

// Problem constants: B=8, H=W=64, N=4096, C=256, nh=8, nh2=4, hd=32, sr=8
#define BATCH 8
#define NTOK 4096
#define CH 256

// ---------------------------------------------------------------------------
// Scratch (device globals)
// ---------------------------------------------------------------------------
__device__ uint32_t g_xp  [(size_t)BATCH * NTOK * CH];   // x packed (hi,lo)
__device__ uint32_t g_qp  [(size_t)BATCH * NTOK * CH];   // q packed
__device__ uint32_t g_catp[(size_t)BATCH * NTOK * CH];   // cat packed
__device__ uint32_t g_x1p [BATCH * 256 * CH];
__device__ uint32_t g_x2p [BATCH * 64 * CH];
__device__ float    g_kv1 [BATCH * 256 * CH];
__device__ float    g_kv2 [BATCH * 64 * CH];
__device__ uint32_t g_k1p [BATCH * 256 * 128];
__device__ uint32_t g_k2p [BATCH * 64 * 128];
__device__ uint32_t g_v1p [BATCH * 4 * 32 * 256];        // V^T packed [b,h][e][s]
__device__ uint32_t g_v2p [BATCH * 4 * 32 * 64];
// weight splits
__device__ __nv_bfloat16 g_qwh [256 * 256], g_qwl [256 * 256];
__device__ __nv_bfloat16 g_k1wh[256 * 256], g_k1wl[256 * 256];
__device__ __nv_bfloat16 g_k2wh[256 * 256], g_k2wl[256 * 256];
__device__ __nv_bfloat16 g_pwh [256 * 256], g_pwl [256 * 256];

// ---------------------------------------------------------------------------
// helpers
// ---------------------------------------------------------------------------
__device__ __forceinline__ uint32_t pack_hilo(float v) {
    __nv_bfloat16 h = __float2bfloat16(v);
    __nv_bfloat16 l = __float2bfloat16(v - __bfloat162float(h));
    return (uint32_t)__bfloat16_as_ushort(h) |
           ((uint32_t)__bfloat16_as_ushort(l) << 16);
}

// Pack two fp32 into bf16x2 hi-pair and residual lo-pair (elem0 in low half).
__device__ __forceinline__ void pack2_hilo(
    float p0, float p1, uint32_t& h, uint32_t& l)
{
    uint32_t hp;
    asm("cvt.rn.bf16x2.f32 %0, %1, %2;" : "=r"(hp) : "f"(p1), "f"(p0));
    const float r0 = p0 - __uint_as_float(hp << 16);
    const float r1 = p1 - __uint_as_float(hp & 0xffff0000u);
    uint32_t lp;
    asm("cvt.rn.bf16x2.f32 %0, %1, %2;" : "=r"(lp) : "f"(r1), "f"(r0));
    h = hp; l = lp;
}

__device__ __forceinline__ void mma16816(
    float* c, const uint32_t* a, const uint32_t* b)
{
    asm volatile(
        "mma.sync.aligned.m16n8k16.row.col.f32.bf16.bf16.f32 "
        "{%0,%1,%2,%3}, {%4,%5,%6,%7}, {%8,%9}, {%0,%1,%2,%3};"
        : "+f"(c[0]), "+f"(c[1]), "+f"(c[2]), "+f"(c[3])
        : "r"(a[0]), "r"(a[1]), "r"(a[2]), "r"(a[3]), "r"(b[0]), "r"(b[1]));
}

__device__ __forceinline__ void cpa16(void* dst, const void* src) {
    uint32_t d = (uint32_t)__cvta_generic_to_shared(dst);
    asm volatile("cp.async.cg.shared.global [%0], [%1], 16;\n"
                 :: "r"(d), "l"(src));
}

// ---------------------------------------------------------------------------
// Pipelined tensor-core GEMM body (verified). K=256, N=256.
// ---------------------------------------------------------------------------
template<int MODE>
__device__ __forceinline__ void gemm_body(
    const uint32_t* __restrict__ A,
    const __nv_bfloat16* __restrict__ Wh,
    const __nv_bfloat16* __restrict__ Wl,
    const float* __restrict__ bias,
    float* __restrict__ Cf, uint32_t* __restrict__ Cp,
    int m0, char* smraw)
{
    constexpr int LDA = 40;
    constexpr int LDB = 40;
    constexpr int ASZ = 128 * LDA;
    constexpr int BSZ = 256 * LDB;

    uint32_t*      Ap = (uint32_t*)smraw;
    __nv_bfloat16* Bh = (__nv_bfloat16*)(Ap + 3 * ASZ);
    __nv_bfloat16* Bl = Bh + 3 * BSZ;

    const int tid = threadIdx.x;
    const int w = tid >> 5, lane = tid & 31;
    const int wm = w & 3, wn = w >> 2;
    const int g = lane >> 2, qk = (lane & 3) * 2;

    auto load_stage = [&](int s, int k0) {
#pragma unroll
        for (int i = 0; i < 2; i++) {
            const int c = tid + i * 512;
            const int row = c >> 3, ch = c & 7;
            cpa16(&Ap[s * ASZ + row * LDA + ch * 4],
                  &A[(size_t)(m0 + row) * 256 + k0 + ch * 4]);
        }
#pragma unroll
        for (int i = 0; i < 2; i++) {
            const int c = tid + i * 512;
            const int row = c >> 2, ch = c & 3;
            cpa16(&Bh[s * BSZ + row * LDB + ch * 8],
                  &Wh[(size_t)row * 256 + k0 + ch * 8]);
        }
#pragma unroll
        for (int i = 0; i < 2; i++) {
            const int c = tid + i * 512;
            const int row = c >> 2, ch = c & 3;
            cpa16(&Bl[s * BSZ + row * LDB + ch * 8],
                  &Wl[(size_t)row * 256 + k0 + ch * 8]);
        }
        asm volatile("cp.async.commit_group;\n" ::: "memory");
    };

    float acc[2][8][4];
#pragma unroll
    for (int mt = 0; mt < 2; mt++)
#pragma unroll
        for (int nt = 0; nt < 8; nt++)
#pragma unroll
            for (int r = 0; r < 4; r++) acc[mt][nt][r] = 0.f;

    load_stage(0, 0);
    load_stage(1, 32);

    for (int it = 0; it < 8; it++) {
        if (it < 7) asm volatile("cp.async.wait_group 1;\n" ::: "memory");
        else        asm volatile("cp.async.wait_group 0;\n" ::: "memory");
        __syncthreads();
        if (it + 2 < 8) load_stage((it + 2) % 3, (it + 2) * 32);

        const int s = it % 3;
        const uint32_t*      As  = Ap + s * ASZ;
        const __nv_bfloat16* Bhs = Bh + s * BSZ;
        const __nv_bfloat16* Bls = Bl + s * BSZ;

#pragma unroll
        for (int ks = 0; ks < 2; ks++) {
            const int kb = ks * 16;
            uint32_t ah[2][4], al[2][4];
#pragma unroll
            for (int mt = 0; mt < 2; mt++) {
                const int row = wm * 32 + mt * 16 + g;
                uint2 p0 = *(const uint2*)&As[row * LDA + kb + qk];
                uint2 p1 = *(const uint2*)&As[(row + 8) * LDA + kb + qk];
                uint2 p2 = *(const uint2*)&As[row * LDA + kb + qk + 8];
                uint2 p3 = *(const uint2*)&As[(row + 8) * LDA + kb + qk + 8];
                ah[mt][0] = __byte_perm(p0.x, p0.y, 0x5410);
                al[mt][0] = __byte_perm(p0.x, p0.y, 0x7632);
                ah[mt][1] = __byte_perm(p1.x, p1.y, 0x5410);
                al[mt][1] = __byte_perm(p1.x, p1.y, 0x7632);
                ah[mt][2] = __byte_perm(p2.x, p2.y, 0x5410);
                al[mt][2] = __byte_perm(p2.x, p2.y, 0x7632);
                ah[mt][3] = __byte_perm(p3.x, p3.y, 0x5410);
                al[mt][3] = __byte_perm(p3.x, p3.y, 0x7632);
            }
            uint32_t bf[8][2];
#pragma unroll
            for (int nt = 0; nt < 8; nt++) {
                const __nv_bfloat16* pb = &Bhs[(wn * 64 + nt * 8 + g) * LDB + kb + qk];
                bf[nt][0] = *(const uint32_t*)pb;
                bf[nt][1] = *(const uint32_t*)(pb + 8);
            }
#pragma unroll
            for (int mt = 0; mt < 2; mt++)
#pragma unroll
                for (int nt = 0; nt < 8; nt++) {
                    mma16816(acc[mt][nt], ah[mt], bf[nt]);
                    mma16816(acc[mt][nt], al[mt], bf[nt]);
                }
#pragma unroll
            for (int nt = 0; nt < 8; nt++) {
                const __nv_bfloat16* pb = &Bls[(wn * 64 + nt * 8 + g) * LDB + kb + qk];
                bf[nt][0] = *(const uint32_t*)pb;
                bf[nt][1] = *(const uint32_t*)(pb + 8);
            }
#pragma unroll
            for (int mt = 0; mt < 2; mt++)
#pragma unroll
                for (int nt = 0; nt < 8; nt++)
                    mma16816(acc[mt][nt], ah[mt], bf[nt]);
        }
        __syncthreads();
    }

#pragma unroll
    for (int mt = 0; mt < 2; mt++) {
        const int r = m0 + wm * 32 + mt * 16 + g;
#pragma unroll
        for (int nt = 0; nt < 8; nt++) {
            const int col = wn * 64 + nt * 8 + qk;
            if constexpr (MODE == 0) {
                const float b0 = bias[col], b1 = bias[col + 1];
                *(float2*)&Cf[(size_t)r * 256 + col] =
                    make_float2(acc[mt][nt][0] + b0, acc[mt][nt][1] + b1);
                *(float2*)&Cf[(size_t)(r + 8) * 256 + col] =
                    make_float2(acc[mt][nt][2] + b0, acc[mt][nt][3] + b1);
            } else if constexpr (MODE == 1) {
                *(uint2*)&Cp[(size_t)r * 256 + col] =
                    make_uint2(pack_hilo(acc[mt][nt][0]), pack_hilo(acc[mt][nt][1]));
                *(uint2*)&Cp[(size_t)(r + 8) * 256 + col] =
                    make_uint2(pack_hilo(acc[mt][nt][2]), pack_hilo(acc[mt][nt][3]));
            } else {
                *(float2*)&Cf[(size_t)r * 256 + col] =
                    make_float2(acc[mt][nt][0], acc[mt][nt][1]);
                *(float2*)&Cf[(size_t)(r + 8) * 256 + col] =
                    make_float2(acc[mt][nt][2], acc[mt][nt][3]);
                if (col < 128) {
                    *(uint2*)&Cp[(size_t)r * 128 + col] =
                        make_uint2(pack_hilo(acc[mt][nt][0]), pack_hilo(acc[mt][nt][1]));
                    *(uint2*)&Cp[(size_t)(r + 8) * 128 + col] =
                        make_uint2(pack_hilo(acc[mt][nt][2]), pack_hilo(acc[mt][nt][3]));
                }
            }
        }
    }
}

// Combined projection GEMMs: q (256 blocks) + kv1 (16) + kv2 (4).
__global__ __launch_bounds__(512) void gemm_all(
    const uint32_t* __restrict__ xp,
    const uint32_t* __restrict__ x1p, const uint32_t* __restrict__ x2p,
    const __nv_bfloat16* __restrict__ qwh, const __nv_bfloat16* __restrict__ qwl,
    const __nv_bfloat16* __restrict__ k1wh, const __nv_bfloat16* __restrict__ k1wl,
    const __nv_bfloat16* __restrict__ k2wh, const __nv_bfloat16* __restrict__ k2wl,
    uint32_t* __restrict__ qp,
    float* __restrict__ kv1, uint32_t* __restrict__ k1p,
    float* __restrict__ kv2, uint32_t* __restrict__ k2p)
{
    extern __shared__ __align__(16) char smraw[];
    if (blockIdx.x < 256)
        gemm_body<1>(xp, qwh, qwl, nullptr, nullptr, qp, blockIdx.x * 128, smraw);
    else if (blockIdx.x < 272)
        gemm_body<2>(x1p, k1wh, k1wl, nullptr, kv1, k1p, (blockIdx.x - 256) * 128, smraw);
    else
        gemm_body<2>(x2p, k2wh, k2wl, nullptr, kv2, k2p, (blockIdx.x - 272) * 128, smraw);
}

// Output projection.
__global__ __launch_bounds__(512) void gemm_proj(
    const uint32_t* __restrict__ A,
    const __nv_bfloat16* __restrict__ Wh, const __nv_bfloat16* __restrict__ Wl,
    const float* __restrict__ bias, float* __restrict__ Cf)
{
    extern __shared__ __align__(16) char smraw[];
    gemm_body<0>(A, Wh, Wl, bias, Cf, nullptr, blockIdx.x * 128, smraw);
}

// ---------------------------------------------------------------------------
// LN + exact GELU block helper (per 256-thread window group)
// ---------------------------------------------------------------------------
__device__ __forceinline__ float ln_gelu_block(
    float a, const float* __restrict__ g, const float* __restrict__ bln,
    float* red, int c)
{
    float s1 = a, s2 = a * a;
#pragma unroll
    for (int o = 16; o > 0; o >>= 1) {
        s1 += __shfl_xor_sync(0xffffffffu, s1, o);
        s2 += __shfl_xor_sync(0xffffffffu, s2, o);
    }
    if ((c & 31) == 0) { red[c >> 5] = s1; red[8 + (c >> 5)] = s2; }
    __syncthreads();
    if (c == 0) {
        float a0 = 0.f, b0 = 0.f;
#pragma unroll
        for (int i = 0; i < 8; i++) { a0 += red[i]; b0 += red[8 + i]; }
        red[0] = a0; red[8] = b0;
    }
    __syncthreads();
    const float mean = red[0] * (1.f / 256.f);
    const float var  = red[8] * (1.f / 256.f) - mean * mean;
    float y = (a - mean) * rsqrtf(var + 1e-5f) * g[c] + bln[c];
    y = 0.5f * y * (1.0f + erff(y * 0.70710678118654752f));
    __syncthreads();
    return y;
}

// ---------------------------------------------------------------------------
// dwconv_fused + x-pack + weight split (unchanged, verified)
// ---------------------------------------------------------------------------
__global__ __launch_bounds__(512) void dwconv_wsplit(
    const float* __restrict__ x, uint32_t* __restrict__ xp,
    const float* __restrict__ w1, const float* __restrict__ b1c,
    const float* __restrict__ g1, const float* __restrict__ bl1,
    const float* __restrict__ w2, const float* __restrict__ b2c,
    const float* __restrict__ g2, const float* __restrict__ bl2,
    uint32_t* __restrict__ x1p, uint32_t* __restrict__ x2p,
    const float* __restrict__ w0m, const float* __restrict__ w1m,
    const float* __restrict__ w2m, const float* __restrict__ w3m,
    __nv_bfloat16* __restrict__ h0, __nv_bfloat16* __restrict__ l0,
    __nv_bfloat16* __restrict__ h1, __nv_bfloat16* __restrict__ l1,
    __nv_bfloat16* __restrict__ h2, __nv_bfloat16* __restrict__ l2,
    __nv_bfloat16* __restrict__ h3, __nv_bfloat16* __restrict__ l3)
{
    if (blockIdx.x >= 256) {
        const int widx = blockIdx.x - 256;
        const int which = widx >> 7;
        const int i = (widx & 127) * 512 + threadIdx.x;
        const float* in = which == 0 ? w0m : which == 1 ? w1m : which == 2 ? w2m : w3m;
        __nv_bfloat16* oh = which == 0 ? h0 : which == 1 ? h1 : which == 2 ? h2 : h3;
        __nv_bfloat16* ol = which == 0 ? l0 : which == 1 ? l1 : which == 2 ? l2 : l3;
        const float v = in[i];
        const __nv_bfloat16 hi = __float2bfloat16(v);
        oh[i] = hi;
        ol[i] = __float2bfloat16(v - __bfloat162float(hi));
        return;
    }

    extern __shared__ float sw[];
    float* w2s = sw;
    float* w1s = sw + 64 * 257;
    float* redb = sw + 80 * 257;

    const int tid = threadIdx.x;
    const int c = tid & 255;
    const int win = tid >> 8;
    float* red = redb + win * 16;

    const int b = blockIdx.x >> 5;
    const int pair = blockIdx.x & 31;
    const int t2 = pair * 2 + win;
    const int oh2 = t2 >> 3, ow2 = t2 & 7;

    for (int i = tid; i < 64 * 256; i += 512)
        w2s[(i & 63) * 257 + (i >> 6)] = w2[i];
    for (int i = tid; i < 16 * 256; i += 512)
        w1s[(i & 15) * 257 + (i >> 4)] = w1[i];
    __syncthreads();

    float acc2 = b2c[c];
    float acc1[2][2];
    acc1[0][0] = acc1[0][1] = acc1[1][0] = acc1[1][1] = b1c[c];

#pragma unroll
    for (int kh = 0; kh < 8; kh++) {
#pragma unroll
        for (int kw = 0; kw < 8; kw++) {
            const int ih = oh2 * 8 + kh, iw = ow2 * 8 + kw;
            const size_t xi = ((size_t)b * NTOK + ih * 64 + iw) * CH + c;
            const float xv = x[xi];
            xp[xi] = pack_hilo(xv);
            acc2 += xv * w2s[(kh * 8 + kw) * 257 + c];
            acc1[kh >> 2][kw >> 2] += xv * w1s[((kh & 3) * 4 + (kw & 3)) * 257 + c];
        }
    }

    const float y2 = ln_gelu_block(acc2, g2, bl2, red, c);
    x2p[((size_t)b * 64 + t2) * CH + c] = pack_hilo(y2);
#pragma unroll
    for (int i = 0; i < 2; i++)
#pragma unroll
        for (int j = 0; j < 2; j++) {
            const float y1 = ln_gelu_block(acc1[i][j], g1, bl1, red, c);
            const int t1 = (oh2 * 2 + i) * 16 + (ow2 * 2 + j);
            x1p[((size_t)b * 256 + t1) * CH + c] = pack_hilo(y1);
        }
}

// ---------------------------------------------------------------------------
// Fused v local conv (+residual) -> packed V^T [b,h][e][s] (unchanged)
// ---------------------------------------------------------------------------
__global__ __launch_bounds__(128) void vconv_fused(
    const float* __restrict__ kv1, const float* __restrict__ lcw1,
    const float* __restrict__ lcb1, uint32_t* __restrict__ v1p,
    const float* __restrict__ kv2, const float* __restrict__ lcw2,
    const float* __restrict__ lcb2, uint32_t* __restrict__ v2p)
{
    int token, HS;
    const float *kv, *lcw, *lcb;
    uint32_t* vtp;
    if (blockIdx.x < BATCH * 256) {
        token = blockIdx.x; HS = 16; kv = kv1; lcw = lcw1; lcb = lcb1; vtp = v1p;
    } else {
        token = blockIdx.x - BATCH * 256; HS = 8; kv = kv2; lcw = lcw2; lcb = lcb2; vtp = v2p;
    }
    const int NS = HS * HS;
    const int b  = token / NS;
    const int s  = token - b * NS;
    const int hs = s / HS, ws = s - hs * HS;
    const int c  = threadIdx.x;

    float acc = lcb[c];
#pragma unroll
    for (int kh = 0; kh < 3; kh++)
#pragma unroll
        for (int kw = 0; kw < 3; kw++) {
            const int ih = hs - 1 + kh, iw = ws - 1 + kw;
            if (ih >= 0 && ih < HS && iw >= 0 && iw < HS)
                acc += kv[((size_t)b * NS + ih * HS + iw) * 256 + 128 + c]
                     * lcw[c * 9 + kh * 3 + kw];
        }
    const float v = kv[(size_t)token * 256 + 128 + c] + acc;
    const int h = c >> 5, e = c & 31;
    vtp[(((size_t)b * 4 + h) * 32 + e) * NS + s] = pack_hilo(v);
}

// ---------------------------------------------------------------------------
// Flash attention v2: 64 q / 256 threads / 2 blocks per SM.
// cp.async split groups: QK (group 0) waits before phase 1; V (group 1)
// streams into a DEDICATED buffer during phase 1. 8 warps = 2m x 4n.
// ---------------------------------------------------------------------------
template<int NS>
__global__ __launch_bounds__(256, 2) void attn_flash(
    const uint32_t* __restrict__ qp,
    const uint32_t* __restrict__ kp,
    const uint32_t* __restrict__ vtp,
    uint32_t* __restrict__ catp,
    int qoff, int ooff)
{
    constexpr int SCH = NS / 4;        // s per warp chunk
    constexpr int NT2 = SCH / 8;       // n8 tiles per warp (phase 1)
    constexpr int KT  = SCH / 16;      // k16 tiles per warp (phase 3)
    constexpr int LDQ = 36;            // row stride (16B aligned)
    constexpr int VSP = NS + 4;        // V row stride (16B aligned)
    constexpr int CHK = NS / 4;        // 16B chunks per V row
    // smem word layout
    constexpr int OFF_KS = 64 * LDQ;
    constexpr int OFF_VS = OFF_KS + NS * LDQ;
    constexpr int VEND   = OFF_VS + 32 * VSP;
    constexpr int OFF_PB = (OFF_VS >= 8704) ? 0 : VEND;   // alias dead Q/K if fits
    constexpr int PBEND  = OFF_PB + 8 * 32 * 34;
    constexpr int OFF_ST = (PBEND > VEND) ? PBEND : VEND;
    const float kfac = 0.17677669529663689f * 1.4426950408889634f;

    extern __shared__ float smf[];
    uint32_t* SM  = (uint32_t*)smf;
    uint32_t* Qs  = SM;                 // [64][LDQ]  (dead after phase 1)
    uint32_t* Ks  = SM + OFF_KS;        // [NS][LDQ]  (dead after phase 1)
    uint32_t* Vs  = SM + OFF_VS;        // [32][VSP]  dedicated
    float*    pb  = smf + OFF_PB;       // [8][32][34] partial O
    float*    mx  = smf + OFF_ST;       // [4][64]
    float*    smr = smf + OFF_ST + 256; // [4][64]

    const int b = blockIdx.x >> 2, h = blockIdx.x & 3;
    const int q0 = blockIdx.y * 64;
    const int tid = threadIdx.x, lane = tid & 31, w = tid >> 5;
    const int g = lane >> 2, qk = (lane & 3) * 2;
    const int wm = w >> 2, wn = w & 3;

    // ---- async staging: QK (group 0), V (group 1) ----
#pragma unroll 2
    for (int c = tid; c < 64 * 8; c += 256) {
        const int r = c >> 3, cw = c & 7;
        cpa16(&Qs[r * LDQ + cw * 4],
              &qp[((size_t)(b * 4096 + q0 + r)) * 256 + qoff + h * 32 + cw * 4]);
    }
    for (int c = tid; c < NS * 8; c += 256) {
        const int s = c >> 3, cw = c & 7;
        cpa16(&Ks[s * LDQ + cw * 4],
              &kp[((size_t)(b * NS + s)) * 128 + h * 32 + cw * 4]);
    }
    asm volatile("cp.async.commit_group;\n" ::: "memory");
    for (int c = tid; c < 32 * CHK; c += 256) {
        const int e = c / CHK, s4 = c % CHK;
        cpa16(&Vs[e * VSP + s4 * 4],
              &vtp[(((size_t)(b * 4 + h)) * 32 + e) * NS + s4 * 4]);
    }
    asm volatile("cp.async.commit_group;\n" ::: "memory");
    asm volatile("cp.async.wait_group 1;\n" ::: "memory");   // QK ready; V in flight
    __syncthreads();

    // ---- phase 1: S = Q K^T into registers ----
    float acc[2][NT2][4];
#pragma unroll
    for (int mt = 0; mt < 2; mt++)
#pragma unroll
        for (int nt = 0; nt < NT2; nt++)
#pragma unroll
            for (int r = 0; r < 4; r++) acc[mt][nt][r] = 0.f;

#pragma unroll
    for (int kc = 0; kc < 2; kc++) {
        const int kb = kc * 16;
        uint32_t ah[2][4], al[2][4];
#pragma unroll
        for (int mt = 0; mt < 2; mt++) {
            const int row = wm * 32 + mt * 16 + g;
            uint2 p0 = *(const uint2*)&Qs[row * LDQ + kb + qk];
            uint2 p1 = *(const uint2*)&Qs[(row + 8) * LDQ + kb + qk];
            uint2 p2 = *(const uint2*)&Qs[row * LDQ + kb + qk + 8];
            uint2 p3 = *(const uint2*)&Qs[(row + 8) * LDQ + kb + qk + 8];
            ah[mt][0] = __byte_perm(p0.x, p0.y, 0x5410);
            al[mt][0] = __byte_perm(p0.x, p0.y, 0x7632);
            ah[mt][1] = __byte_perm(p1.x, p1.y, 0x5410);
            al[mt][1] = __byte_perm(p1.x, p1.y, 0x7632);
            ah[mt][2] = __byte_perm(p2.x, p2.y, 0x5410);
            al[mt][2] = __byte_perm(p2.x, p2.y, 0x7632);
            ah[mt][3] = __byte_perm(p3.x, p3.y, 0x5410);
            al[mt][3] = __byte_perm(p3.x, p3.y, 0x7632);
        }
#pragma unroll
        for (int nt = 0; nt < NT2; nt++) {
            const int srow = wn * SCH + nt * 8 + g;
            uint2 p0 = *(const uint2*)&Ks[srow * LDQ + kb + qk];
            uint2 p1 = *(const uint2*)&Ks[srow * LDQ + kb + qk + 8];
            uint32_t bh[2], bl[2];
            bh[0] = __byte_perm(p0.x, p0.y, 0x5410);
            bl[0] = __byte_perm(p0.x, p0.y, 0x7632);
            bh[1] = __byte_perm(p1.x, p1.y, 0x5410);
            bl[1] = __byte_perm(p1.x, p1.y, 0x7632);
#pragma unroll
            for (int mt = 0; mt < 2; mt++) {
                mma16816(acc[mt][nt], ah[mt], bh);
                mma16816(acc[mt][nt], al[mt], bh);
                mma16816(acc[mt][nt], ah[mt], bl);
            }
        }
    }

    // ---- chunk max ----
#pragma unroll
    for (int mt = 0; mt < 2; mt++)
#pragma unroll
        for (int half = 0; half < 2; half++) {
            float m = acc[mt][0][half * 2];
#pragma unroll
            for (int nt = 0; nt < NT2; nt++) {
                m = fmaxf(m, acc[mt][nt][half * 2]);
                m = fmaxf(m, acc[mt][nt][half * 2 + 1]);
            }
            m = fmaxf(m, __shfl_xor_sync(0xffffffffu, m, 1));
            m = fmaxf(m, __shfl_xor_sync(0xffffffffu, m, 2));
            if ((lane & 3) == 0)
                mx[wn * 64 + wm * 32 + mt * 16 + half * 8 + g] = m;
        }
    __syncthreads();   // barrier 1: maxima visible; Q/K dead

    // ---- global max, exp in registers, chunk sums ----
#pragma unroll
    for (int mt = 0; mt < 2; mt++)
#pragma unroll
        for (int half = 0; half < 2; half++) {
            const int row = wm * 32 + mt * 16 + half * 8 + g;
            float m = fmaxf(fmaxf(mx[row], mx[64 + row]),
                            fmaxf(mx[128 + row], mx[192 + row]));
            float s = 0.f;
#pragma unroll
            for (int nt = 0; nt < NT2; nt++) {
                float e0 = exp2f((acc[mt][nt][half * 2]     - m) * kfac);
                float e1 = exp2f((acc[mt][nt][half * 2 + 1] - m) * kfac);
                acc[mt][nt][half * 2]     = e0;
                acc[mt][nt][half * 2 + 1] = e1;
                s += e0 + e1;
            }
            s += __shfl_xor_sync(0xffffffffu, s, 1);
            s += __shfl_xor_sync(0xffffffffu, s, 2);
            if ((lane & 3) == 0) smr[wn * 64 + row] = s;
        }
    asm volatile("cp.async.wait_group 0;\n" ::: "memory");   // V ready
    __syncthreads();   // barrier 2: sums + V visible

    // ---- phase 3: O_partial = P V over this warp's s-chunk ----
    float acc3[2][4][4];
#pragma unroll
    for (int mt = 0; mt < 2; mt++)
#pragma unroll
        for (int nt = 0; nt < 4; nt++)
#pragma unroll
            for (int r = 0; r < 4; r++) acc3[mt][nt][r] = 0.f;

#pragma unroll
    for (int kt = 0; kt < KT; kt++) {
        uint32_t bh[4][2], bl[4][2];
#pragma unroll
        for (int nt3 = 0; nt3 < 4; nt3++) {
            const int e = nt3 * 8 + g;
            const int base = e * VSP + wn * SCH + kt * 16 + qk;
            uint2 p0 = *(const uint2*)&Vs[base];
            uint2 p1 = *(const uint2*)&Vs[base + 8];
            bh[nt3][0] = __byte_perm(p0.x, p0.y, 0x5410);
            bl[nt3][0] = __byte_perm(p0.x, p0.y, 0x7632);
            bh[nt3][1] = __byte_perm(p1.x, p1.y, 0x5410);
            bl[nt3][1] = __byte_perm(p1.x, p1.y, 0x7632);
        }
#pragma unroll
        for (int mt = 0; mt < 2; mt++) {
            uint32_t ah[4], al[4];
            pack2_hilo(acc[mt][2 * kt][0],     acc[mt][2 * kt][1],     ah[0], al[0]);
            pack2_hilo(acc[mt][2 * kt][2],     acc[mt][2 * kt][3],     ah[1], al[1]);
            pack2_hilo(acc[mt][2 * kt + 1][0], acc[mt][2 * kt + 1][1], ah[2], al[2]);
            pack2_hilo(acc[mt][2 * kt + 1][2], acc[mt][2 * kt + 1][3], ah[3], al[3]);
#pragma unroll
            for (int nt3 = 0; nt3 < 4; nt3++) {
                mma16816(acc3[mt][nt3], ah, bh[nt3]);
                mma16816(acc3[mt][nt3], al, bh[nt3]);
                mma16816(acc3[mt][nt3], ah, bl[nt3]);
            }
        }
    }

    // write partials (slot = wn*2 + wm)
#pragma unroll
    for (int mt = 0; mt < 2; mt++)
#pragma unroll
        for (int nt3 = 0; nt3 < 4; nt3++) {
            const int rl = mt * 16 + g;
            const int base = ((wn * 2 + wm) * 32 + rl) * 34 + nt3 * 8 + qk;
            *(float2*)&pb[base] = make_float2(acc3[mt][nt3][0], acc3[mt][nt3][1]);
            *(float2*)&pb[base + 8 * 34] = make_float2(acc3[mt][nt3][2], acc3[mt][nt3][3]);
        }
    __syncthreads();   // barrier 3: partials visible

    // ---- reduction + epilogue: warp (wm, wn) -> rows wm*32..+32, e = wn*8..+8
#pragma unroll
    for (int rr = 0; rr < 4; rr++) {
        const int rloc = rr * 8 + (lane >> 2);
        const int row = wm * 32 + rloc;
        const int cl = wn * 8 + (lane & 3) * 2;
        float ox = 0.f, oy = 0.f;
#pragma unroll
        for (int wv = 0; wv < 4; wv++) {
            float2 p = *(const float2*)&pb[((wv * 2 + wm) * 32 + rloc) * 34 + cl];
            ox += p.x; oy += p.y;
        }
        const float inv = 1.0f / (smr[row] + smr[64 + row] +
                                  smr[128 + row] + smr[192 + row]);
        const int col = ooff + h * 32 + cl;
        *(uint2*)&catp[((size_t)(b * 4096 + q0 + row)) * 256 + col] =
            make_uint2(pack_hilo(ox * inv), pack_hilo(oy * inv));
    }
}

// ---------------------------------------------------------------------------
// launch
// ---------------------------------------------------------------------------
extern "C" void kernel_launch(void* const* d_in, const int* in_sizes, int n_in,
                              void* d_out, int out_size)
{
    const float* x      = (const float*)d_in[0];
    const float* q_w    = (const float*)d_in[1];
    const float* kv1_w  = (const float*)d_in[2];
    const float* kv2_w  = (const float*)d_in[3];
    const float* proj_w = (const float*)d_in[4];
    const float* proj_b = (const float*)d_in[5];
    const float* sr1_w  = (const float*)d_in[6];
    const float* sr1_b  = (const float*)d_in[7];
    const float* sr2_w  = (const float*)d_in[8];
    const float* sr2_b  = (const float*)d_in[9];
    const float* ln1_g  = (const float*)d_in[10];
    const float* ln1_b  = (const float*)d_in[11];
    const float* ln2_g  = (const float*)d_in[12];
    const float* ln2_b  = (const float*)d_in[13];
    const float* lc1_w  = (const float*)d_in[14];
    const float* lc1_b  = (const float*)d_in[15];
    const float* lc2_w  = (const float*)d_in[16];
    const float* lc2_b  = (const float*)d_in[17];
    float* out = (float*)d_out;

    uint32_t *p_xp, *p_qp, *p_catp, *p_x1p, *p_x2p, *p_k1p, *p_k2p, *p_v1p, *p_v2p;
    float *p_kv1, *p_kv2;
    __nv_bfloat16 *p_qwh, *p_qwl, *p_k1wh, *p_k1wl, *p_k2wh, *p_k2wl, *p_pwh, *p_pwl;
    cudaGetSymbolAddress((void**)&p_xp,   g_xp);
    cudaGetSymbolAddress((void**)&p_qp,   g_qp);
    cudaGetSymbolAddress((void**)&p_catp, g_catp);
    cudaGetSymbolAddress((void**)&p_x1p,  g_x1p);
    cudaGetSymbolAddress((void**)&p_x2p,  g_x2p);
    cudaGetSymbolAddress((void**)&p_kv1,  g_kv1);
    cudaGetSymbolAddress((void**)&p_kv2,  g_kv2);
    cudaGetSymbolAddress((void**)&p_k1p,  g_k1p);
    cudaGetSymbolAddress((void**)&p_k2p,  g_k2p);
    cudaGetSymbolAddress((void**)&p_v1p,  g_v1p);
    cudaGetSymbolAddress((void**)&p_v2p,  g_v2p);
    cudaGetSymbolAddress((void**)&p_qwh,  g_qwh);
    cudaGetSymbolAddress((void**)&p_qwl,  g_qwl);
    cudaGetSymbolAddress((void**)&p_k1wh, g_k1wh);
    cudaGetSymbolAddress((void**)&p_k1wl, g_k1wl);
    cudaGetSymbolAddress((void**)&p_k2wh, g_k2wh);
    cudaGetSymbolAddress((void**)&p_k2wl, g_k2wl);
    cudaGetSymbolAddress((void**)&p_pwh,  g_pwh);
    cudaGetSymbolAddress((void**)&p_pwl,  g_pwl);

    const int smem_gemm = 3 * (128 * 40 * 4) + 2 * (3 * 256 * 40 * 2);  // 184,320
    const int smem_dw   = 80 * 257 * 4 + 128;
    // attn_flash smem (words -> bytes), mirrors kernel constexpr layout:
    // NS=256: OFF_VS = 64*36 + 256*36 = 11520, VEND = 11520+32*260 = 19840,
    //         pb aliases 0, OFF_ST = 19840, total = 20352 w = 81408 B (x2/SM)
    const int smem_a1 = 20352 * 4;
    // NS=64:  OFF_VS = 2304+2304 = 4608, VEND = 4608+32*68 = 6784,
    //         OFF_PB = 6784, PBEND = 15488, OFF_ST = 15488, total = 16000 w
    const int smem_a2 = 16000 * 4;
    cudaFuncSetAttribute(gemm_all,  cudaFuncAttributeMaxDynamicSharedMemorySize, smem_gemm);
    cudaFuncSetAttribute(gemm_proj, cudaFuncAttributeMaxDynamicSharedMemorySize, smem_gemm);
    cudaFuncSetAttribute(dwconv_wsplit, cudaFuncAttributeMaxDynamicSharedMemorySize, smem_dw);
    cudaFuncSetAttribute(attn_flash<256>, cudaFuncAttributeMaxDynamicSharedMemorySize, smem_a1);
    cudaFuncSetAttribute(attn_flash<64>,  cudaFuncAttributeMaxDynamicSharedMemorySize, smem_a2);

    // 0: dwconv (+x pack) + weight split
    dwconv_wsplit<<<768, 512, smem_dw>>>(
        x, p_xp, sr1_w, sr1_b, ln1_g, ln1_b, sr2_w, sr2_b, ln2_g, ln2_b,
        p_x1p, p_x2p,
        q_w, kv1_w, kv2_w, proj_w,
        p_qwh, p_qwl, p_k1wh, p_k1wl, p_k2wh, p_k2wl, p_pwh, p_pwl);
    // 1: all projections (q + kv1 + kv2)
    gemm_all<<<276, 512, smem_gemm>>>(
        p_xp, p_x1p, p_x2p, p_qwh, p_qwl, p_k1wh, p_k1wl, p_k2wh, p_k2wl,
        p_qp, p_kv1, p_k1p, p_kv2, p_k2p);
    // 2: v local conv -> packed V^T
    vconv_fused<<<BATCH * 256 + BATCH * 64, 128>>>(
        p_kv1, lc1_w, lc1_b, p_v1p, p_kv2, lc2_w, lc2_b, p_v2p);
    // 3: attention branch 1 (PROFILED SLOT)
    attn_flash<256><<<dim3(32, 64), 256, smem_a1>>>(p_qp, p_k1p, p_v1p, p_catp, 0,   0);
    // 4: attention branch 2
    attn_flash<64 ><<<dim3(32, 64), 256, smem_a2>>>(p_qp, p_k2p, p_v2p, p_catp, 128, 128);
    // 5: output projection
    gemm_proj<<<256, 512, smem_gemm>>>(p_catp, p_pwh, p_pwl, proj_b, out);
}